// round 14
// baseline (speedup 1.0000x reference)
#include <cuda_runtime.h>
#include <cuda_fp16.h>
#include <math.h>
#include <stdint.h>

#define Cc   256
#define Hh   100
#define Ww   100
#define Pp   10000
#define Tt   25
#define MIDc 32
#define GRP  8
#define EPSv 1e-5f

#define PW    102
#define CH    10752
#define NB    10200
#define WSCALE 64.f
#define WINV   0.015625f

// ---------------- scratch ----------------
__device__ __align__(16) __half g_xT[3*Pp*Cc];      // cur,h0,h1 pixel-major fp16
__device__ __align__(16) __half g_padT[2*CH*Cc];    // conv inputs (padded, pixel-major)
__device__ __align__(16) __half g_owh[64*512];
__device__ __align__(16) __half g_owl[64*512];
__device__ __align__(16) __half g_w1h[9*Cc*Cc];
__device__ __align__(16) __half g_w1l[9*Cc*Cc];
__device__ __align__(16) __half g_w2h[9*Cc*Cc];
__device__ __align__(16) __half g_w2l[9*Cc*Cc];
__device__ float  g_offA[2*50*Pp];
__device__ float  g_offB[2*50*Pp];
__device__ float  g_dwT[Tt*Cc];
__device__ float  g_aligned[2*Cc*Pp];
__device__ float  g_y[2*Cc*Pp];
__device__ float  g_red[2][2*Cc];                   // RAW SUMS (atomic accumulated)
__device__ float  g_attn[2][Cc];
__device__ float2 g_stat[3*Cc];
__device__ float  g_gn[2*2*GRP];

// ---------------- helpers ----------------
__device__ __forceinline__ uint32_t smem_u32(const void* p) {
    uint32_t a;
    asm("{ .reg .u64 t; cvta.to.shared.u64 t, %1; cvt.u32.u64 %0, t; }" : "=r"(a) : "l"(p));
    return a;
}
__device__ __forceinline__ void ldsm4(uint32_t* r, uint32_t addr) {
    asm volatile("ldmatrix.sync.aligned.m8n8.x4.shared.b16 {%0,%1,%2,%3}, [%4];"
        : "=r"(r[0]), "=r"(r[1]), "=r"(r[2]), "=r"(r[3]) : "r"(addr));
}
__device__ __forceinline__ void mma16816h(float* c, uint32_t a0, uint32_t a1,
                                          uint32_t a2, uint32_t a3,
                                          uint32_t b0, uint32_t b1)
{
    asm volatile(
        "mma.sync.aligned.m16n8k16.row.col.f32.f16.f16.f32 "
        "{%0,%1,%2,%3}, {%4,%5,%6,%7}, {%8,%9}, {%0,%1,%2,%3};"
        : "+f"(c[0]), "+f"(c[1]), "+f"(c[2]), "+f"(c[3])
        : "r"(a0), "r"(a1), "r"(a2), "r"(a3), "r"(b0), "r"(b1));
}
__device__ __forceinline__ void cp16(uint32_t dst, const void* src) {
    asm volatile("cp.async.cg.shared.global [%0], [%1], 16;" :: "r"(dst), "l"(src));
}
#define CP_COMMIT() asm volatile("cp.async.commit_group;" ::: "memory")
#define CP_WAIT0()  asm volatile("cp.async.wait_group 0;" ::: "memory")

// ------- prep: weight splits + dwT + zero stats/red + zero pad border -----------
__global__ void prep_w_kernel(const float* __restrict__ w1,
                              const float* __restrict__ w2,
                              const float* __restrict__ ow,
                              const float* __restrict__ dw)
{
    const int n = Cc*Cc*9;
    int i = blockIdx.x*256 + threadIdx.x;
    if (i < 3*Cc) g_stat[i] = make_float2(0.f, 0.f);
    if (i < 4*Cc) ((float*)g_red)[i] = 0.f;
    if (i < 2*n) {
        int which = (i >= n);
        int ii = which ? i - n : i;
        float v = (which ? w2[ii] : w1[ii]) * WSCALE;
        int oc = ii / (Cc*9);
        int rem = ii % (Cc*9);
        int ic = rem / 9;
        int t  = rem % 9;
        __half hi = __float2half_rn(v);
        __half lo = __float2half_rn(v - __half2float(hi));
        int dst = (t*Cc + oc)*Cc + ic;
        if (which) { g_w2h[dst] = hi; g_w2l[dst] = lo; }
        else       { g_w1h[dst] = hi; g_w1l[dst] = lo; }
        return;
    }
    int j = i - 2*n;
    if (j < 64*512) {
        int row = j >> 9;
        float v = (row < 50) ? ow[j]*WSCALE : 0.f;
        __half hi = __float2half_rn(v);
        __half lo = __float2half_rn(v - __half2float(hi));
        g_owh[j] = hi;
        g_owl[j] = lo;
        return;
    }
    int k = j - 64*512;
    if (k < Tt*Cc) {
        int t = k / Cc, c = k % Cc;
        g_dwT[k] = dw[c*Tt + t];
        return;
    }
    int z = k - Tt*Cc;                 // border zeroing: 2*CH*Cc elements
    if (z < 2*CH*Cc) {
        int buf = z / (CH*Cc);
        int rem = z - buf*CH*Cc;
        int gp = rem >> 8, c = rem & 255;
        int y = gp / PW, x = gp - y*PW;
        bool interior = (y >= 1 && y <= 100 && x >= 1 && x <= 100);
        if (!interior) g_padT[buf*CH*Cc + gp*Cc + c] = __float2half(0.f);
    }
}

// ------- transpose to fp16 pixel-major ----------------
__global__ void split_xT_kernel(const float* __restrict__ cur,
                                const float* __restrict__ h0,
                                const float* __restrict__ h1)
{
    __shared__ float tile[32][33];
    int z = blockIdx.z;
    const float* src = (z == 0) ? cur : (z == 1) ? h0 : h1;
    __half* dst = g_xT + z*Pp*Cc;
    int p0 = blockIdx.x*32, c0 = blockIdx.y*32;
    int tx = threadIdx.x, ty = threadIdx.y;
    #pragma unroll
    for (int i = ty; i < 32; i += 8) {
        int p = p0 + tx;
        tile[i][tx] = (p < Pp) ? src[(c0+i)*Pp + p] : 0.f;
    }
    __syncthreads();
    #pragma unroll
    for (int i = ty; i < 32; i += 8) {
        int p = p0 + i;
        if (p < Pp) dst[p*Cc + c0 + tx] = __float2half(tile[tx][i]);
    }
}

// ---------------- offset 1x1 conv: fp16 2-pass, K-split(y), hist(z) -------------
__global__ void __launch_bounds__(256)
offset_mma_kernel(const float* __restrict__ bias)
{
    __shared__ __align__(16) __half s_ah[64][24], s_al[64][24];
    __shared__ __align__(16) __half s_b[128][24];
    int p0 = blockIdx.x*128;
    int ks = blockIdx.y;
    int h  = blockIdx.z;
    const __half* x = (ks == 0) ? g_xT : (g_xT + (1+h)*Pp*Cc);
    float* outp = (ks == 0) ? (g_offA + h*50*Pp) : (g_offB + h*50*Pp);
    int kbase = ks*256;
    int tid = threadIdx.x;
    int wid = tid >> 5, lane = tid & 31;
    int wm = wid & 1, wn = wid >> 1;
    int k0 = (lane & 3)*2, grp = lane >> 2;

    float acc[2][4][4];
    #pragma unroll
    for (int mt = 0; mt < 2; mt++)
        #pragma unroll
        for (int nt = 0; nt < 4; nt++)
            #pragma unroll
            for (int r = 0; r < 4; r++) acc[mt][nt][r] = 0.f;

    for (int kk = 0; kk < 256; kk += 16) {
        __syncthreads();
        {
            int bufsel = tid >> 7, rem = tid & 127;
            int m = rem >> 1, half = rem & 1;
            const __half* src = bufsel ? g_owl : g_owh;
            uint4 v = *(const uint4*)&src[m*512 + kbase + kk + half*8];
            __half* dst = bufsel ? &s_al[m][half*8] : &s_ah[m][half*8];
            *(uint4*)dst = v;
        }
        {
            int pos = tid >> 1, half = tid & 1;
            int p = p0 + pos;
            uint4 v = make_uint4(0u,0u,0u,0u);
            if (p < Pp) v = *(const uint4*)&x[p*Cc + kk + half*8];
            *(uint4*)&s_b[pos][half*8] = v;
        }
        __syncthreads();

        uint32_t ah[2][4], al2[2][4], bf[4][2];
        #pragma unroll
        for (int mt = 0; mt < 2; mt++) {
            int m = wm*32 + mt*16 + grp;
            ah[mt][0] = *(const uint32_t*)&s_ah[m][k0];
            ah[mt][1] = *(const uint32_t*)&s_ah[m+8][k0];
            ah[mt][2] = *(const uint32_t*)&s_ah[m][k0+8];
            ah[mt][3] = *(const uint32_t*)&s_ah[m+8][k0+8];
            al2[mt][0] = *(const uint32_t*)&s_al[m][k0];
            al2[mt][1] = *(const uint32_t*)&s_al[m+8][k0];
            al2[mt][2] = *(const uint32_t*)&s_al[m][k0+8];
            al2[mt][3] = *(const uint32_t*)&s_al[m+8][k0+8];
        }
        #pragma unroll
        for (int nt = 0; nt < 4; nt++) {
            int n = wn*32 + nt*8 + grp;
            bf[nt][0] = *(const uint32_t*)&s_b[n][k0];
            bf[nt][1] = *(const uint32_t*)&s_b[n][k0+8];
        }
        #pragma unroll
        for (int mt = 0; mt < 2; mt++)
            #pragma unroll
            for (int nt = 0; nt < 4; nt++) {
                mma16816h(acc[mt][nt], ah[mt][0], ah[mt][1], ah[mt][2], ah[mt][3], bf[nt][0], bf[nt][1]);
                mma16816h(acc[mt][nt], al2[mt][0], al2[mt][1], al2[mt][2], al2[mt][3], bf[nt][0], bf[nt][1]);
            }
    }
    #pragma unroll
    for (int mt = 0; mt < 2; mt++)
        #pragma unroll
        for (int nt = 0; nt < 4; nt++)
            #pragma unroll
            for (int r = 0; r < 4; r++) {
                int j = wm*32 + mt*16 + grp + ((r >= 2) ? 8 : 0);
                int p = p0 + wn*32 + nt*8 + (lane & 3)*2 + (r & 1);
                if (j < 50 && p < Pp) {
                    float v = acc[mt][nt][r] * WINV;
                    if (ks == 0) v += bias[j];
                    outp[j*Pp + p] = v;
                }
            }
}

// ------ deformable depthwise conv + fused per-channel reductions ---------------
__global__ void deform_kernel()
{
    __shared__ float s_dw[Tt*Cc];
    __shared__ int   s_base[8][Tt][4];
    __shared__ float s_wt[8][Tt][4];
    __shared__ float s_t1[8][Cc];
    __shared__ float s_t2[8][Cc];
    int h = blockIdx.y;
    const __half* histT = g_xT + (1+h)*Pp*Cc;
    const float* offA = g_offA + h*50*Pp;
    const float* offB = g_offB + h*50*Pp;
    float* alignedp = g_aligned + h*Cc*Pp;
    int p0 = blockIdx.x*8;
    int tid = threadIdx.x;
    for (int i = tid; i < Tt*Cc; i += 256) s_dw[i] = g_dwT[i];
    if (tid < 200) {
        int pi = tid / 25, t = tid % 25;
        int p = p0 + pi;
        int y = p / Ww, x = p % Ww;
        float dy = offA[(2*t)*Pp + p]   + offB[(2*t)*Pp + p];
        float dx = offA[(2*t+1)*Pp + p] + offB[(2*t+1)*Pp + p];
        float ys = (float)(y + t/5 - 2) + dy;
        float xs = (float)(x + t%5 - 2) + dx;
        float y0 = floorf(ys), x0 = floorf(xs);
        float wy = ys - y0, wx = xs - x0;
        float cy[2] = {y0, y0+1.f}, cx[2] = {x0, x0+1.f};
        float wyv[2] = {1.f-wy, wy}, wxv[2] = {1.f-wx, wx};
        #pragma unroll
        for (int a = 0; a < 2; a++)
        #pragma unroll
        for (int bq = 0; bq < 2; bq++) {
            int k = a*2 + bq;
            bool valid = (cy[a] >= 0.f) && (cy[a] <= 99.f) &&
                         (cx[bq] >= 0.f) && (cx[bq] <= 99.f);
            int yi = (int)fminf(fmaxf(cy[a], 0.f), 99.f);
            int xi = (int)fminf(fmaxf(cx[bq], 0.f), 99.f);
            s_base[pi][t][k] = (yi*Ww + xi)*Cc;
            s_wt[pi][t][k]   = valid ? wyv[a]*wxv[bq] : 0.f;
        }
    }
    __syncthreads();
    int pi = tid >> 5;
    int cq = (tid & 31) << 3;
    int p = p0 + pi;
    float acc[8];
    #pragma unroll
    for (int i = 0; i < 8; i++) acc[i] = 0.f;
    #pragma unroll 5
    for (int t = 0; t < Tt; t++) {
        float sv[8];
        #pragma unroll
        for (int i = 0; i < 8; i++) sv[i] = 0.f;
        #pragma unroll
        for (int k = 0; k < 4; k++) {
            float wv = s_wt[pi][t][k];
            uint4 raw = *(const uint4*)(histT + s_base[pi][t][k] + cq);
            const __half2* hp = (const __half2*)&raw;
            #pragma unroll
            for (int q = 0; q < 4; q++) {
                float2 f = __half22float2(hp[q]);
                sv[2*q]   += wv*f.x;
                sv[2*q+1] += wv*f.y;
            }
        }
        const float4* dwp = (const float4*)&s_dw[t*Cc + cq];
        float4 d0 = dwp[0], d1 = dwp[1];
        acc[0] += d0.x*sv[0]; acc[1] += d0.y*sv[1];
        acc[2] += d0.z*sv[2]; acc[3] += d0.w*sv[3];
        acc[4] += d1.x*sv[4]; acc[5] += d1.y*sv[5];
        acc[6] += d1.z*sv[6]; acc[7] += d1.w*sv[7];
    }
    #pragma unroll
    for (int i = 0; i < 8; i++)
        alignedp[(cq+i)*Pp + p] = acc[i];
    // fused reduction: sum(cur - aligned), sum |cur - hist| per channel
    {
        uint4 rawc = *(const uint4*)(g_xT + p*Cc + cq);
        uint4 rawh = *(const uint4*)(histT + p*Cc + cq);
        const __half2* hc = (const __half2*)&rawc;
        const __half2* hh = (const __half2*)&rawh;
        float t1[8], t2[8];
        #pragma unroll
        for (int q = 0; q < 4; q++) {
            float2 fc = __half22float2(hc[q]);
            float2 fh = __half22float2(hh[q]);
            t1[2*q]   = fc.x - acc[2*q];
            t1[2*q+1] = fc.y - acc[2*q+1];
            t2[2*q]   = fabsf(fc.x - fh.x);
            t2[2*q+1] = fabsf(fc.y - fh.y);
        }
        *(float4*)&s_t1[pi][cq]     = make_float4(t1[0], t1[1], t1[2], t1[3]);
        *(float4*)&s_t1[pi][cq+4]   = make_float4(t1[4], t1[5], t1[6], t1[7]);
        *(float4*)&s_t2[pi][cq]     = make_float4(t2[0], t2[1], t2[2], t2[3]);
        *(float4*)&s_t2[pi][cq+4]   = make_float4(t2[4], t2[5], t2[6], t2[7]);
    }
    __syncthreads();
    {
        int c = tid;
        float s1 = 0.f, s2 = 0.f;
        #pragma unroll
        for (int q = 0; q < 8; q++) { s1 += s_t1[q][c]; s2 += s_t2[q][c]; }
        atomicAdd(&g_red[h][c], s1);
        atomicAdd(&g_red[h][Cc + c], s2);
    }
}

// ---------------- channel attention for BOTH hists ------------------------------
__global__ void attn_kernel(const float* __restrict__ w1,
                            const float* __restrict__ w2)
{
    __shared__ float s_pool[Cc];
    __shared__ float s_hid[MIDc];
    int tid = threadIdx.x;
    const float inv = 1.f/(float)Pp;
    for (int h = 0; h < 2; h++) {
        s_pool[tid] = g_red[h][tid] * inv;
        __syncthreads();
        if (tid < MIDc) {
            float a = 0.f;
            #pragma unroll 8
            for (int c2 = 0; c2 < Cc; c2++) a += w1[tid*Cc + c2]*s_pool[c2];
            s_hid[tid] = fmaxf(a, 0.f);
        }
        __syncthreads();
        float a = 0.f;
        #pragma unroll
        for (int m = 0; m < MIDc; m++) a += w2[tid*MIDc + m]*s_hid[m];
        g_attn[h][tid] = 1.f/(1.f + expf(-a));
        __syncthreads();
    }
}

// ---------------- fused = cur + aligned*attn -> padded fp16 ---------------------
__global__ void fuse1T_kernel(const float* __restrict__ cur)
{
    __shared__ float tc[32][33], ta[32][33];
    int h = blockIdx.z;
    const float* alignedp = g_aligned + h*Cc*Pp;
    __half* dst = g_padT + h*CH*Cc;
    int p0 = blockIdx.x*32, c0 = blockIdx.y*32;
    int tx = threadIdx.x, ty = threadIdx.y;
    #pragma unroll
    for (int i = ty; i < 32; i += 8) {
        int p = p0 + tx;
        tc[i][tx] = (p < Pp) ? cur[(c0+i)*Pp + p] : 0.f;
        ta[i][tx] = (p < Pp) ? alignedp[(c0+i)*Pp + p] : 0.f;
    }
    __syncthreads();
    #pragma unroll
    for (int i = ty; i < 32; i += 8) {
        int p = p0 + i;
        if (p < Pp) {
            int c = c0 + tx;
            float f = tc[tx][i] + ta[tx][i]*g_attn[h][c];
            int y = p / Ww, x = p - y*Ww;
            int gp = (y+1)*PW + x + 1;
            dst[gp*Cc + c] = __float2half(f);
        }
    }
}

// ---------------- conv3x3: fp16 2-pass, M=32 tile, occ 3, cp.async --------------
#define SA_ELE (9*32*16)                 // 4608 halfs per (hi|lo) buffer
#define STAGE_ELE (2*SA_ELE + 396*16)    // 15552 halfs
#define STAGE_BYTES (STAGE_ELE*2)        // 31104
#define CONV_SMEM (2*STAGE_BYTES)        // 62208

__global__ void __launch_bounds__(256, 3)
conv3x3_mma_kernel(const __half* __restrict__ wh,
                   const __half* __restrict__ wl,
                   const __half* __restrict__ in_base,
                   float* __restrict__ out_base,
                   float2* __restrict__ stat_base)
{
    extern __shared__ __half sm2[];
    uint32_t s0 = smem_u32(sm2);

    int z = blockIdx.z;
    const __half* inp = in_base + z*CH*Cc;
    float* out = out_base + z*Cc*Pp;
    float2* stat = stat_base + z*Cc;

    int b0  = blockIdx.x*128;
    int oc0 = blockIdx.y*32;
    int tid = threadIdx.x;
    int wid = tid >> 5, lane = tid & 31;
    int wn = wid;                        // 8 warps x 16 positions

    float acc[2][2][4];
    #pragma unroll
    for (int mt = 0; mt < 2; mt++)
        #pragma unroll
        for (int nt = 0; nt < 2; nt++)
            #pragma unroll
            for (int r = 0; r < 4; r++) acc[mt][nt][r] = 0.f;

    int a_lrow = lane & 15;
    int a_ksel = (lane >> 4) & 1;
    int b_tile = lane >> 3;
    int b_r    = lane & 7;
    int b_ntof = (b_tile >> 1)*8;
    int b_ks   = b_tile & 1;

    auto issue = [&](int ic0, int buf) {
        uint32_t base = s0 + buf*STAGE_BYTES;
        uint32_t sbh = base;
        uint32_t sbl = base + SA_ELE*2;
        uint32_t sbb = base + 2*SA_ELE*2;
        for (int i = tid; i < 576; i += 256) {
            int row = i >> 1, half = i & 1;
            int t = row >> 5, m = row & 31;
            int src = (t*Cc + oc0 + m)*Cc + ic0 + half*8;
            uint32_t doff = (uint32_t)((row*16 + half*8)*2);
            cp16(sbh + doff, wh + src);
            cp16(sbl + doff, wl + src);
        }
        for (int i = tid; i < 792; i += 256) {
            int row = i >> 1, half = i & 1;
            int prow = row / 132;
            int col  = row - prow*132;
            int src = (b0 + prow*PW + col)*Cc + ic0 + half*8;
            cp16(sbb + (uint32_t)((row*16 + half*8)*2), inp + src);
        }
        CP_COMMIT();
    };

    issue(0, 0);
    for (int s = 0; s < 16; s++) {
        CP_WAIT0();
        __syncthreads();
        if (s < 15) issue((s+1)*16, (s+1) & 1);

        uint32_t base = s0 + (s & 1)*STAGE_BYTES;
        uint32_t sa_h = base;
        uint32_t sa_l = base + SA_ELE*2;
        uint32_t sb   = base + 2*SA_ELE*2;

        #pragma unroll
        for (int t = 0; t < 9; t++) {
            uint32_t ah[2][4], al2[2][4];
            #pragma unroll
            for (int mt = 0; mt < 2; mt++) {
                uint32_t aoff = (uint32_t)(((t*32 + mt*16 + a_lrow)*16 + a_ksel*8)*2);
                ldsm4(ah[mt],  sa_h + aoff);
                ldsm4(al2[mt], sa_l + aoff);
            }
            int posb = (t/3)*132 + (t%3) + wn*16;
            uint32_t bf[2][2];
            {
                int row = posb + b_ntof + b_r;
                uint32_t addr = sb + (uint32_t)((row*16 + b_ks*8)*2);
                uint32_t rr[4];
                ldsm4(rr, addr);
                bf[0][0] = rr[0]; bf[0][1] = rr[1];
                bf[1][0] = rr[2]; bf[1][1] = rr[3];
            }
            #pragma unroll
            for (int mt = 0; mt < 2; mt++)
                #pragma unroll
                for (int nt = 0; nt < 2; nt++)
                    mma16816h(acc[mt][nt], ah[mt][0], ah[mt][1], ah[mt][2], ah[mt][3], bf[nt][0], bf[nt][1]);
            #pragma unroll
            for (int mt = 0; mt < 2; mt++)
                #pragma unroll
                for (int nt = 0; nt < 2; nt++)
                    mma16816h(acc[mt][nt], al2[mt][0], al2[mt][1], al2[mt][2], al2[mt][3], bf[nt][0], bf[nt][1]);
        }
        __syncthreads();
    }
    const unsigned FULL = 0xFFFFFFFFu;
    #pragma unroll
    for (int mt = 0; mt < 2; mt++) {
        #pragma unroll
        for (int rh = 0; rh < 2; rh++) {
            int m = oc0 + mt*16 + (lane >> 2) + rh*8;
            float s = 0.f, ss = 0.f;
            #pragma unroll
            for (int nt = 0; nt < 2; nt++) {
                #pragma unroll
                for (int rl = 0; rl < 2; rl++) {
                    float val = acc[mt][nt][rh*2 + rl] * WINV;
                    int n = wn*16 + nt*8 + (lane & 3)*2 + rl;
                    int b = b0 + n;
                    int y = b / PW;
                    int x = b - y*PW;
                    if (b < NB && x < Ww) {
                        out[m*Pp + y*Ww + x] = val;
                        s += val; ss += val*val;
                    }
                }
            }
            s  += __shfl_down_sync(FULL, s, 2);
            s  += __shfl_down_sync(FULL, s, 1);
            ss += __shfl_down_sync(FULL, ss, 2);
            ss += __shfl_down_sync(FULL, ss, 1);
            if ((lane & 3) == 0) {
                atomicAdd(&stat[m].x, s);
                atomicAdd(&stat[m].y, ss);
            }
        }
    }
}

// ---- GN (inline group-stat fold) + weighted fuse -> conv3 input ----------------
__global__ void gn_norm_comb_kernel(const float* __restrict__ gng,
                                    const float* __restrict__ gnb)
{
    __shared__ float tY0[32][33], tY1[32][33];
    __shared__ float s_ms[2][2];
    int p0 = blockIdx.x*32, c0 = blockIdx.y*32;
    int tx = threadIdx.x, ty = threadIdx.y;
    int ltid = ty*32 + tx;
    // fold stats for THIS block's group (g == blockIdx.y): warps 0,1 for h0,h1
    if (ltid < 64) {
        int h = ltid >> 5, lane = ltid & 31;
        float2 v = g_stat[h*Cc + c0 + lane];
        float s = v.x, ss = v.y;
        #pragma unroll
        for (int o = 16; o > 0; o >>= 1) {
            s  += __shfl_down_sync(0xFFFFFFFFu, s, o);
            ss += __shfl_down_sync(0xFFFFFFFFu, ss, o);
        }
        if (lane == 0) {
            const float N = 32.f*(float)Pp;
            float m = s/N;
            s_ms[h][0] = m;
            s_ms[h][1] = ss/N - m*m;
        }
    }
    #pragma unroll
    for (int i = ty; i < 32; i += 8) {
        int p = p0 + tx;
        tY0[i][tx] = (p < Pp) ? g_y[(c0+i)*Pp + p] : 0.f;
        tY1[i][tx] = (p < Pp) ? g_y[Cc*Pp + (c0+i)*Pp + p] : 0.f;
    }
    __syncthreads();
    int c = c0 + tx;
    const float inv = 1.f/(float)Pp;
    float wgt0 = 1.f/(1.f + expf(g_red[0][Cc + c]*inv));
    float wgt1 = 1.f/(1.f + expf(g_red[1][Cc + c]*inv));
    float winv = 1.f/(wgt0 + wgt1 + 1e-6f);
    float gg = gng[c], gb = gnb[c];
    float m0 = s_ms[0][0], r0 = rsqrtf(s_ms[0][1] + EPSv);
    float m1 = s_ms[1][0], r1 = rsqrtf(s_ms[1][1] + EPSv);
    #pragma unroll
    for (int i = ty; i < 32; i += 8) {
        int p = p0 + i;
        if (p < Pp) {
            float h0 = fmaxf((tY0[tx][i] - m0)*r0*gg + gb, 0.f);
            float h1 = fmaxf((tY1[tx][i] - m1)*r1*gg + gb, 0.f);
            float f = (h0*wgt0 + h1*wgt1) * winv;
            int y = p / Ww, x = p - y*Ww;
            int gp = (y+1)*PW + x + 1;
            g_padT[gp*Cc + c] = __float2half(f);
        }
    }
}

// ---------------- BN normalize + relu -> output ----------------
__global__ void bn_norm_kernel(const float* __restrict__ bng,
                               const float* __restrict__ bnb,
                               float* __restrict__ out)
{
    int i = blockIdx.x*256 + threadIdx.x;
    int c = i / Pp;
    float2 st = g_stat[2*Cc + c];
    float m = st.x * (1.f/(float)Pp);
    float v = st.y * (1.f/(float)Pp) - m*m;
    float o = (g_y[i] - m)*rsqrtf(v + EPSv)*bng[c] + bnb[c];
    out[i] = fmaxf(o, 0.f);
}

// ---------------- host launcher ----------------
extern "C" void kernel_launch(void* const* d_in, const int* in_sizes, int n_in,
                              void* d_out, int out_size)
{
    const float* cur      = (const float*)d_in[0];
    const float* hist0    = (const float*)d_in[1];
    const float* hist1    = (const float*)d_in[2];
    const float* offset_w = (const float*)d_in[3];
    const float* offset_b = (const float*)d_in[4];
    const float* deform_w = (const float*)d_in[5];
    const float* ca_w1    = (const float*)d_in[6];
    const float* ca_w2    = (const float*)d_in[7];
    const float* out_w    = (const float*)d_in[8];
    const float* gn_g     = (const float*)d_in[9];
    const float* gn_b     = (const float*)d_in[10];
    const float* fuse_w   = (const float*)d_in[11];
    const float* bn_g     = (const float*)d_in[12];
    const float* bn_b     = (const float*)d_in[13];
    float* out = (float*)d_out;

    float *p_y;
    float2 *p_stat;
    __half *p_w1h, *p_w1l, *p_w2h, *p_w2l, *p_padT;
    cudaGetSymbolAddress((void**)&p_y, g_y);
    cudaGetSymbolAddress((void**)&p_stat, g_stat);
    cudaGetSymbolAddress((void**)&p_w1h, g_w1h);
    cudaGetSymbolAddress((void**)&p_w1l, g_w1l);
    cudaGetSymbolAddress((void**)&p_w2h, g_w2h);
    cudaGetSymbolAddress((void**)&p_w2l, g_w2l);
    cudaGetSymbolAddress((void**)&p_padT, g_padT);

    cudaFuncSetAttribute(conv3x3_mma_kernel,
                         cudaFuncAttributeMaxDynamicSharedMemorySize, CONV_SMEM);

    dim3 tGrid(313, 8, 3), tBlock(32, 8);
    dim3 fuseGrid(313, 8, 2);
    dim3 gnGrid(313, 8);
    dim3 offGrid(79, 2, 2);
    dim3 convGrid(80, 8, 2);
    dim3 conv3Grid(80, 8, 1);
    const int NW = Cc*Cc*9;
    const int PREP_TOT = 2*NW + 64*512 + Tt*Cc + 2*CH*Cc;

    split_xT_kernel<<<tGrid, tBlock>>>(cur, hist0, hist1);                    // 0
    prep_w_kernel<<<(PREP_TOT + 255)/256, 256>>>(out_w, fuse_w, offset_w, deform_w); // 1
    offset_mma_kernel<<<offGrid, 256>>>(offset_b);                            // 2
    deform_kernel<<<dim3(1250, 2), 256>>>();                                  // 3 (profiled)
    attn_kernel<<<1, Cc>>>(ca_w1, ca_w2);                                     // 4
    fuse1T_kernel<<<fuseGrid, tBlock>>>(cur);                                 // 5
    conv3x3_mma_kernel<<<convGrid, 256, CONV_SMEM>>>(p_w1h, p_w1l, p_padT, p_y, p_stat); // 6
    gn_norm_comb_kernel<<<gnGrid, tBlock>>>(gn_g, gn_b);                      // 7
    conv3x3_mma_kernel<<<conv3Grid, 256, CONV_SMEM>>>(p_w2h, p_w2l, p_padT, p_y, p_stat + 2*Cc); // 8
    bn_norm_kernel<<<Cc*Pp/256, 256>>>(bn_g, bn_b, out);                      // 9
}

// round 15
// speedup vs baseline: 1.1646x; 1.1646x over previous
#include <cuda_runtime.h>
#include <cuda_fp16.h>
#include <math.h>
#include <stdint.h>

#define Cc   256
#define Hh   100
#define Ww   100
#define Pp   10000
#define Tt   25
#define MIDc 32
#define GRP  8
#define EPSv 1e-5f

#define PW    102
#define CH    10752
#define NB    10200
#define WSCALE 64.f
#define WINV   0.015625f

// ---------------- scratch ----------------
__device__ __align__(16) __half g_xT[3*Pp*Cc];      // cur,h0,h1 pixel-major fp16
__device__ __align__(16) __half g_padT[2*CH*Cc];    // conv inputs (padded, pixel-major)
__device__ __align__(16) __half g_owh[64*512];
__device__ __align__(16) __half g_owl[64*512];
__device__ __align__(16) __half g_w1h[9*Cc*Cc];
__device__ __align__(16) __half g_w1l[9*Cc*Cc];
__device__ __align__(16) __half g_w2h[9*Cc*Cc];
__device__ __align__(16) __half g_w2l[9*Cc*Cc];
__device__ float  g_offA[2*50*Pp];
__device__ float  g_offB[2*50*Pp];
__device__ float  g_dwT[Tt*Cc];
__device__ float  g_aligned[2*Cc*Pp];
__device__ float  g_y[2*Cc*Pp];
__device__ float  g_red[2][2*Cc];                   // RAW SUMS (atomic accumulated)
__device__ float  g_attn[2][Cc];
__device__ float2 g_stat[3*Cc];

// ---------------- helpers ----------------
__device__ __forceinline__ uint32_t smem_u32(const void* p) {
    uint32_t a;
    asm("{ .reg .u64 t; cvta.to.shared.u64 t, %1; cvt.u32.u64 %0, t; }" : "=r"(a) : "l"(p));
    return a;
}
__device__ __forceinline__ void ldsm4(uint32_t* r, uint32_t addr) {
    asm volatile("ldmatrix.sync.aligned.m8n8.x4.shared.b16 {%0,%1,%2,%3}, [%4];"
        : "=r"(r[0]), "=r"(r[1]), "=r"(r[2]), "=r"(r[3]) : "r"(addr));
}
__device__ __forceinline__ void mma16816h(float* c, uint32_t a0, uint32_t a1,
                                          uint32_t a2, uint32_t a3,
                                          uint32_t b0, uint32_t b1)
{
    asm volatile(
        "mma.sync.aligned.m16n8k16.row.col.f32.f16.f16.f32 "
        "{%0,%1,%2,%3}, {%4,%5,%6,%7}, {%8,%9}, {%0,%1,%2,%3};"
        : "+f"(c[0]), "+f"(c[1]), "+f"(c[2]), "+f"(c[3])
        : "r"(a0), "r"(a1), "r"(a2), "r"(a3), "r"(b0), "r"(b1));
}
__device__ __forceinline__ void cp16(uint32_t dst, const void* src) {
    asm volatile("cp.async.cg.shared.global [%0], [%1], 16;" :: "r"(dst), "l"(src));
}
#define CP_COMMIT() asm volatile("cp.async.commit_group;" ::: "memory")
#define CP_WAIT0()  asm volatile("cp.async.wait_group 0;" ::: "memory")

// ------- prep: weight splits + dwT + zero stats/red + zero pad border -----------
__global__ void prep_w_kernel(const float* __restrict__ w1,
                              const float* __restrict__ w2,
                              const float* __restrict__ ow,
                              const float* __restrict__ dw)
{
    const int n = Cc*Cc*9;
    int i = blockIdx.x*256 + threadIdx.x;
    if (i < 3*Cc) g_stat[i] = make_float2(0.f, 0.f);
    if (i < 4*Cc) ((float*)g_red)[i] = 0.f;
    if (i < 2*n) {
        int which = (i >= n);
        int ii = which ? i - n : i;
        float v = (which ? w2[ii] : w1[ii]) * WSCALE;
        int oc = ii / (Cc*9);
        int rem = ii % (Cc*9);
        int ic = rem / 9;
        int t  = rem % 9;
        __half hi = __float2half_rn(v);
        __half lo = __float2half_rn(v - __half2float(hi));
        int dst = (t*Cc + oc)*Cc + ic;
        if (which) { g_w2h[dst] = hi; g_w2l[dst] = lo; }
        else       { g_w1h[dst] = hi; g_w1l[dst] = lo; }
        return;
    }
    int j = i - 2*n;
    if (j < 64*512) {
        int row = j >> 9;
        float v = (row < 50) ? ow[j]*WSCALE : 0.f;
        __half hi = __float2half_rn(v);
        __half lo = __float2half_rn(v - __half2float(hi));
        g_owh[j] = hi;
        g_owl[j] = lo;
        return;
    }
    int k = j - 64*512;
    if (k < Tt*Cc) {
        int t = k / Cc, c = k % Cc;
        g_dwT[k] = dw[c*Tt + t];
        return;
    }
    int z = k - Tt*Cc;
    if (z < 2*CH*Cc) {
        int buf = z / (CH*Cc);
        int rem = z - buf*CH*Cc;
        int gp = rem >> 8, c = rem & 255;
        int y = gp / PW, x = gp - y*PW;
        bool interior = (y >= 1 && y <= 100 && x >= 1 && x <= 100);
        if (!interior) g_padT[buf*CH*Cc + gp*Cc + c] = __float2half(0.f);
    }
}

// ------- transpose to fp16 pixel-major ----------------
__global__ void split_xT_kernel(const float* __restrict__ cur,
                                const float* __restrict__ h0,
                                const float* __restrict__ h1)
{
    __shared__ float tile[32][33];
    int z = blockIdx.z;
    const float* src = (z == 0) ? cur : (z == 1) ? h0 : h1;
    __half* dst = g_xT + z*Pp*Cc;
    int p0 = blockIdx.x*32, c0 = blockIdx.y*32;
    int tx = threadIdx.x, ty = threadIdx.y;
    #pragma unroll
    for (int i = ty; i < 32; i += 8) {
        int p = p0 + tx;
        tile[i][tx] = (p < Pp) ? src[(c0+i)*Pp + p] : 0.f;
    }
    __syncthreads();
    #pragma unroll
    for (int i = ty; i < 32; i += 8) {
        int p = p0 + i;
        if (p < Pp) dst[p*Cc + c0 + tx] = __float2half(tile[tx][i]);
    }
}

// ---------------- offset 1x1 conv: fp16 2-pass, K-split(y), hist(z) -------------
__global__ void __launch_bounds__(256)
offset_mma_kernel(const float* __restrict__ bias)
{
    __shared__ __align__(16) __half s_ah[64][24], s_al[64][24];
    __shared__ __align__(16) __half s_b[128][24];
    int p0 = blockIdx.x*128;
    int ks = blockIdx.y;
    int h  = blockIdx.z;
    const __half* x = (ks == 0) ? g_xT : (g_xT + (1+h)*Pp*Cc);
    float* outp = (ks == 0) ? (g_offA + h*50*Pp) : (g_offB + h*50*Pp);
    int kbase = ks*256;
    int tid = threadIdx.x;
    int wid = tid >> 5, lane = tid & 31;
    int wm = wid & 1, wn = wid >> 1;
    int k0 = (lane & 3)*2, grp = lane >> 2;

    float acc[2][4][4];
    #pragma unroll
    for (int mt = 0; mt < 2; mt++)
        #pragma unroll
        for (int nt = 0; nt < 4; nt++)
            #pragma unroll
            for (int r = 0; r < 4; r++) acc[mt][nt][r] = 0.f;

    for (int kk = 0; kk < 256; kk += 16) {
        __syncthreads();
        {
            int bufsel = tid >> 7, rem = tid & 127;
            int m = rem >> 1, half = rem & 1;
            const __half* src = bufsel ? g_owl : g_owh;
            uint4 v = *(const uint4*)&src[m*512 + kbase + kk + half*8];
            __half* dst = bufsel ? &s_al[m][half*8] : &s_ah[m][half*8];
            *(uint4*)dst = v;
        }
        {
            int pos = tid >> 1, half = tid & 1;
            int p = p0 + pos;
            uint4 v = make_uint4(0u,0u,0u,0u);
            if (p < Pp) v = *(const uint4*)&x[p*Cc + kk + half*8];
            *(uint4*)&s_b[pos][half*8] = v;
        }
        __syncthreads();

        uint32_t ah[2][4], al2[2][4], bf[4][2];
        #pragma unroll
        for (int mt = 0; mt < 2; mt++) {
            int m = wm*32 + mt*16 + grp;
            ah[mt][0] = *(const uint32_t*)&s_ah[m][k0];
            ah[mt][1] = *(const uint32_t*)&s_ah[m+8][k0];
            ah[mt][2] = *(const uint32_t*)&s_ah[m][k0+8];
            ah[mt][3] = *(const uint32_t*)&s_ah[m+8][k0+8];
            al2[mt][0] = *(const uint32_t*)&s_al[m][k0];
            al2[mt][1] = *(const uint32_t*)&s_al[m+8][k0];
            al2[mt][2] = *(const uint32_t*)&s_al[m][k0+8];
            al2[mt][3] = *(const uint32_t*)&s_al[m+8][k0+8];
        }
        #pragma unroll
        for (int nt = 0; nt < 4; nt++) {
            int n = wn*32 + nt*8 + grp;
            bf[nt][0] = *(const uint32_t*)&s_b[n][k0];
            bf[nt][1] = *(const uint32_t*)&s_b[n][k0+8];
        }
        #pragma unroll
        for (int mt = 0; mt < 2; mt++)
            #pragma unroll
            for (int nt = 0; nt < 4; nt++) {
                mma16816h(acc[mt][nt], ah[mt][0], ah[mt][1], ah[mt][2], ah[mt][3], bf[nt][0], bf[nt][1]);
                mma16816h(acc[mt][nt], al2[mt][0], al2[mt][1], al2[mt][2], al2[mt][3], bf[nt][0], bf[nt][1]);
            }
    }
    #pragma unroll
    for (int mt = 0; mt < 2; mt++)
        #pragma unroll
        for (int nt = 0; nt < 4; nt++)
            #pragma unroll
            for (int r = 0; r < 4; r++) {
                int j = wm*32 + mt*16 + grp + ((r >= 2) ? 8 : 0);
                int p = p0 + wn*32 + nt*8 + (lane & 3)*2 + (r & 1);
                if (j < 50 && p < Pp) {
                    float v = acc[mt][nt][r] * WINV;
                    if (ks == 0) v += bias[j];
                    outp[j*Pp + p] = v;
                }
            }
}

// ------ deformable depthwise conv + fused per-channel reductions ---------------
__global__ void deform_kernel()
{
    __shared__ float s_dw[Tt*Cc];
    __shared__ int   s_base[8][Tt][4];
    __shared__ float s_wt[8][Tt][4];
    __shared__ float s_t1[8][Cc];
    __shared__ float s_t2[8][Cc];
    int h = blockIdx.y;
    const __half* histT = g_xT + (1+h)*Pp*Cc;
    const float* offA = g_offA + h*50*Pp;
    const float* offB = g_offB + h*50*Pp;
    float* alignedp = g_aligned + h*Cc*Pp;
    int p0 = blockIdx.x*8;
    int tid = threadIdx.x;
    for (int i = tid; i < Tt*Cc; i += 256) s_dw[i] = g_dwT[i];
    if (tid < 200) {
        int pi = tid / 25, t = tid % 25;
        int p = p0 + pi;
        int y = p / Ww, x = p % Ww;
        float dy = offA[(2*t)*Pp + p]   + offB[(2*t)*Pp + p];
        float dx = offA[(2*t+1)*Pp + p] + offB[(2*t+1)*Pp + p];
        float ys = (float)(y + t/5 - 2) + dy;
        float xs = (float)(x + t%5 - 2) + dx;
        float y0 = floorf(ys), x0 = floorf(xs);
        float wy = ys - y0, wx = xs - x0;
        float cy[2] = {y0, y0+1.f}, cx[2] = {x0, x0+1.f};
        float wyv[2] = {1.f-wy, wy}, wxv[2] = {1.f-wx, wx};
        #pragma unroll
        for (int a = 0; a < 2; a++)
        #pragma unroll
        for (int bq = 0; bq < 2; bq++) {
            int k = a*2 + bq;
            bool valid = (cy[a] >= 0.f) && (cy[a] <= 99.f) &&
                         (cx[bq] >= 0.f) && (cx[bq] <= 99.f);
            int yi = (int)fminf(fmaxf(cy[a], 0.f), 99.f);
            int xi = (int)fminf(fmaxf(cx[bq], 0.f), 99.f);
            s_base[pi][t][k] = (yi*Ww + xi)*Cc;
            s_wt[pi][t][k]   = valid ? wyv[a]*wxv[bq] : 0.f;
        }
    }
    __syncthreads();
    int pi = tid >> 5;
    int cq = (tid & 31) << 3;
    int p = p0 + pi;
    float acc[8];
    #pragma unroll
    for (int i = 0; i < 8; i++) acc[i] = 0.f;
    #pragma unroll 5
    for (int t = 0; t < Tt; t++) {
        float sv[8];
        #pragma unroll
        for (int i = 0; i < 8; i++) sv[i] = 0.f;
        #pragma unroll
        for (int k = 0; k < 4; k++) {
            float wv = s_wt[pi][t][k];
            uint4 raw = *(const uint4*)(histT + s_base[pi][t][k] + cq);
            const __half2* hp = (const __half2*)&raw;
            #pragma unroll
            for (int q = 0; q < 4; q++) {
                float2 f = __half22float2(hp[q]);
                sv[2*q]   += wv*f.x;
                sv[2*q+1] += wv*f.y;
            }
        }
        const float4* dwp = (const float4*)&s_dw[t*Cc + cq];
        float4 d0 = dwp[0], d1 = dwp[1];
        acc[0] += d0.x*sv[0]; acc[1] += d0.y*sv[1];
        acc[2] += d0.z*sv[2]; acc[3] += d0.w*sv[3];
        acc[4] += d1.x*sv[4]; acc[5] += d1.y*sv[5];
        acc[6] += d1.z*sv[6]; acc[7] += d1.w*sv[7];
    }
    #pragma unroll
    for (int i = 0; i < 8; i++)
        alignedp[(cq+i)*Pp + p] = acc[i];
    // fused reduction: sum(cur - aligned), sum |cur - hist| per channel
    {
        uint4 rawc = *(const uint4*)(g_xT + p*Cc + cq);
        uint4 rawh = *(const uint4*)(histT + p*Cc + cq);
        const __half2* hc = (const __half2*)&rawc;
        const __half2* hh = (const __half2*)&rawh;
        float t1[8], t2[8];
        #pragma unroll
        for (int q = 0; q < 4; q++) {
            float2 fc = __half22float2(hc[q]);
            float2 fh = __half22float2(hh[q]);
            t1[2*q]   = fc.x - acc[2*q];
            t1[2*q+1] = fc.y - acc[2*q+1];
            t2[2*q]   = fabsf(fc.x - fh.x);
            t2[2*q+1] = fabsf(fc.y - fh.y);
        }
        *(float4*)&s_t1[pi][cq]     = make_float4(t1[0], t1[1], t1[2], t1[3]);
        *(float4*)&s_t1[pi][cq+4]   = make_float4(t1[4], t1[5], t1[6], t1[7]);
        *(float4*)&s_t2[pi][cq]     = make_float4(t2[0], t2[1], t2[2], t2[3]);
        *(float4*)&s_t2[pi][cq+4]   = make_float4(t2[4], t2[5], t2[6], t2[7]);
    }
    __syncthreads();
    {
        int c = tid;
        float s1 = 0.f, s2 = 0.f;
        #pragma unroll
        for (int q = 0; q < 8; q++) { s1 += s_t1[q][c]; s2 += s_t2[q][c]; }
        atomicAdd(&g_red[h][c], s1);
        atomicAdd(&g_red[h][Cc + c], s2);
    }
}

// ---------------- channel attention for BOTH hists ------------------------------
__global__ void attn_kernel(const float* __restrict__ w1,
                            const float* __restrict__ w2)
{
    __shared__ float s_pool[Cc];
    __shared__ float s_hid[MIDc];
    int tid = threadIdx.x;
    const float inv = 1.f/(float)Pp;
    for (int h = 0; h < 2; h++) {
        s_pool[tid] = g_red[h][tid] * inv;
        __syncthreads();
        if (tid < MIDc) {
            float a = 0.f;
            #pragma unroll 8
            for (int c2 = 0; c2 < Cc; c2++) a += w1[tid*Cc + c2]*s_pool[c2];
            s_hid[tid] = fmaxf(a, 0.f);
        }
        __syncthreads();
        float a = 0.f;
        #pragma unroll
        for (int m = 0; m < MIDc; m++) a += w2[tid*MIDc + m]*s_hid[m];
        g_attn[h][tid] = 1.f/(1.f + expf(-a));
        __syncthreads();
    }
}

// ---------------- fused = cur + aligned*attn -> padded fp16 ---------------------
__global__ void fuse1T_kernel(const float* __restrict__ cur)
{
    __shared__ float tc[32][33], ta[32][33];
    int h = blockIdx.z;
    const float* alignedp = g_aligned + h*Cc*Pp;
    __half* dst = g_padT + h*CH*Cc;
    int p0 = blockIdx.x*32, c0 = blockIdx.y*32;
    int tx = threadIdx.x, ty = threadIdx.y;
    #pragma unroll
    for (int i = ty; i < 32; i += 8) {
        int p = p0 + tx;
        tc[i][tx] = (p < Pp) ? cur[(c0+i)*Pp + p] : 0.f;
        ta[i][tx] = (p < Pp) ? alignedp[(c0+i)*Pp + p] : 0.f;
    }
    __syncthreads();
    #pragma unroll
    for (int i = ty; i < 32; i += 8) {
        int p = p0 + i;
        if (p < Pp) {
            int c = c0 + tx;
            float f = tc[tx][i] + ta[tx][i]*g_attn[h][c];
            int y = p / Ww, x = p - y*Ww;
            int gp = (y+1)*PW + x + 1;
            dst[gp*Cc + c] = __float2half(f);
        }
    }
}

// ---------------- conv3x3: fp16 2-pass, M=64 tile, occ 2, cp.async --------------
#define SA_ELE (9*64*16)
#define STAGE_ELE (2*SA_ELE + 396*16)
#define STAGE_BYTES (STAGE_ELE*2)
#define CONV_SMEM (2*STAGE_BYTES)

__global__ void __launch_bounds__(256, 2)
conv3x3_mma_kernel(const __half* __restrict__ wh,
                   const __half* __restrict__ wl,
                   const __half* __restrict__ in_base,
                   float* __restrict__ out_base,
                   float2* __restrict__ stat_base)
{
    extern __shared__ __half sm2[];
    uint32_t s0 = smem_u32(sm2);

    int z = blockIdx.z;
    const __half* inp = in_base + z*CH*Cc;
    float* out = out_base + z*Cc*Pp;
    float2* stat = stat_base + z*Cc;

    int b0  = blockIdx.x*128;
    int oc0 = blockIdx.y*64;
    int tid = threadIdx.x;
    int wid = tid >> 5, lane = tid & 31;
    int wm = wid & 1, wn = wid >> 1;

    float acc[2][4][4];
    #pragma unroll
    for (int mt = 0; mt < 2; mt++)
        #pragma unroll
        for (int nt = 0; nt < 4; nt++)
            #pragma unroll
            for (int r = 0; r < 4; r++) acc[mt][nt][r] = 0.f;

    int a_lrow = lane & 15;
    int a_ksel = (lane >> 4) & 1;
    int b_tile = lane >> 3;
    int b_r    = lane & 7;
    int b_ntof = (b_tile >> 1)*8;
    int b_ks   = b_tile & 1;

    auto issue = [&](int ic0, int buf) {
        uint32_t base = s0 + buf*STAGE_BYTES;
        uint32_t sbh = base;
        uint32_t sbl = base + SA_ELE*2;
        uint32_t sbb = base + 2*SA_ELE*2;
        for (int i = tid; i < 1152; i += 256) {
            int row = i >> 1, half = i & 1;
            int t = row >> 6, m = row & 63;
            int src = (t*Cc + oc0 + m)*Cc + ic0 + half*8;
            uint32_t doff = (uint32_t)((row*16 + half*8)*2);
            cp16(sbh + doff, wh + src);
            cp16(sbl + doff, wl + src);
        }
        for (int i = tid; i < 792; i += 256) {
            int row = i >> 1, half = i & 1;
            int prow = row / 132;
            int col  = row - prow*132;
            int src = (b0 + prow*PW + col)*Cc + ic0 + half*8;
            cp16(sbb + (uint32_t)((row*16 + half*8)*2), inp + src);
        }
        CP_COMMIT();
    };

    issue(0, 0);
    for (int s = 0; s < 16; s++) {
        CP_WAIT0();
        __syncthreads();
        if (s < 15) issue((s+1)*16, (s+1) & 1);

        uint32_t base = s0 + (s & 1)*STAGE_BYTES;
        uint32_t sa_h = base;
        uint32_t sa_l = base + SA_ELE*2;
        uint32_t sb   = base + 2*SA_ELE*2;

        #pragma unroll
        for (int t = 0; t < 9; t++) {
            uint32_t ah[2][4], al2[2][4];
            #pragma unroll
            for (int mt = 0; mt < 2; mt++) {
                uint32_t aoff = (uint32_t)(((t*64 + wm*32 + mt*16 + a_lrow)*16 + a_ksel*8)*2);
                ldsm4(ah[mt],  sa_h + aoff);
                ldsm4(al2[mt], sa_l + aoff);
            }
            int posb = (t/3)*132 + (t%3) + wn*32;
            uint32_t bf[4][2];
            #pragma unroll
            for (int np = 0; np < 2; np++) {
                int row = posb + np*16 + b_ntof + b_r;
                uint32_t addr = sb + (uint32_t)((row*16 + b_ks*8)*2);
                uint32_t rr[4];
                ldsm4(rr, addr);
                bf[2*np][0] = rr[0]; bf[2*np][1] = rr[1];
                bf[2*np+1][0] = rr[2]; bf[2*np+1][1] = rr[3];
            }
            #pragma unroll
            for (int mt = 0; mt < 2; mt++)
                #pragma unroll
                for (int nt = 0; nt < 4; nt++)
                    mma16816h(acc[mt][nt], ah[mt][0], ah[mt][1], ah[mt][2], ah[mt][3], bf[nt][0], bf[nt][1]);
            #pragma unroll
            for (int mt = 0; mt < 2; mt++)
                #pragma unroll
                for (int nt = 0; nt < 4; nt++)
                    mma16816h(acc[mt][nt], al2[mt][0], al2[mt][1], al2[mt][2], al2[mt][3], bf[nt][0], bf[nt][1]);
        }
        __syncthreads();
    }
    const unsigned FULL = 0xFFFFFFFFu;
    #pragma unroll
    for (int mt = 0; mt < 2; mt++) {
        #pragma unroll
        for (int rh = 0; rh < 2; rh++) {
            int m = oc0 + wm*32 + mt*16 + (lane >> 2) + rh*8;
            float s = 0.f, ss = 0.f;
            #pragma unroll
            for (int nt = 0; nt < 4; nt++) {
                #pragma unroll
                for (int rl = 0; rl < 2; rl++) {
                    float val = acc[mt][nt][rh*2 + rl] * WINV;
                    int n = wn*32 + nt*8 + (lane & 3)*2 + rl;
                    int b = b0 + n;
                    int y = b / PW;
                    int x = b - y*PW;
                    if (b < NB && x < Ww) {
                        out[m*Pp + y*Ww + x] = val;
                        s += val; ss += val*val;
                    }
                }
            }
            s  += __shfl_down_sync(FULL, s, 2);
            s  += __shfl_down_sync(FULL, s, 1);
            ss += __shfl_down_sync(FULL, ss, 2);
            ss += __shfl_down_sync(FULL, ss, 1);
            if ((lane & 3) == 0) {
                atomicAdd(&stat[m].x, s);
                atomicAdd(&stat[m].y, ss);
            }
        }
    }
}

// ---- GN (inline group-stat fold) + weighted fuse -> conv3 input ----------------
__global__ void gn_norm_comb_kernel(const float* __restrict__ gng,
                                    const float* __restrict__ gnb)
{
    __shared__ float tY0[32][33], tY1[32][33];
    __shared__ float s_ms[2][2];
    int p0 = blockIdx.x*32, c0 = blockIdx.y*32;
    int tx = threadIdx.x, ty = threadIdx.y;
    int ltid = ty*32 + tx;
    if (ltid < 64) {
        int h = ltid >> 5, lane = ltid & 31;
        float2 v = g_stat[h*Cc + c0 + lane];
        float s = v.x, ss = v.y;
        #pragma unroll
        for (int o = 16; o > 0; o >>= 1) {
            s  += __shfl_down_sync(0xFFFFFFFFu, s, o);
            ss += __shfl_down_sync(0xFFFFFFFFu, ss, o);
        }
        if (lane == 0) {
            const float N = 32.f*(float)Pp;
            float m = s/N;
            s_ms[h][0] = m;
            s_ms[h][1] = ss/N - m*m;
        }
    }
    #pragma unroll
    for (int i = ty; i < 32; i += 8) {
        int p = p0 + tx;
        tY0[i][tx] = (p < Pp) ? g_y[(c0+i)*Pp + p] : 0.f;
        tY1[i][tx] = (p < Pp) ? g_y[Cc*Pp + (c0+i)*Pp + p] : 0.f;
    }
    __syncthreads();
    int c = c0 + tx;
    const float inv = 1.f/(float)Pp;
    float wgt0 = 1.f/(1.f + expf(g_red[0][Cc + c]*inv));
    float wgt1 = 1.f/(1.f + expf(g_red[1][Cc + c]*inv));
    float winv = 1.f/(wgt0 + wgt1 + 1e-6f);
    float gg = gng[c], gb = gnb[c];
    float m0 = s_ms[0][0], r0 = rsqrtf(s_ms[0][1] + EPSv);
    float m1 = s_ms[1][0], r1 = rsqrtf(s_ms[1][1] + EPSv);
    #pragma unroll
    for (int i = ty; i < 32; i += 8) {
        int p = p0 + i;
        if (p < Pp) {
            float h0 = fmaxf((tY0[tx][i] - m0)*r0*gg + gb, 0.f);
            float h1 = fmaxf((tY1[tx][i] - m1)*r1*gg + gb, 0.f);
            float f = (h0*wgt0 + h1*wgt1) * winv;
            int y = p / Ww, x = p - y*Ww;
            int gp = (y+1)*PW + x + 1;
            g_padT[gp*Cc + c] = __float2half(f);
        }
    }
}

// ---------------- BN normalize + relu -> output ----------------
__global__ void bn_norm_kernel(const float* __restrict__ bng,
                               const float* __restrict__ bnb,
                               float* __restrict__ out)
{
    int i = blockIdx.x*256 + threadIdx.x;
    int c = i / Pp;
    float2 st = g_stat[2*Cc + c];
    float m = st.x * (1.f/(float)Pp);
    float v = st.y * (1.f/(float)Pp) - m*m;
    float o = (g_y[i] - m)*rsqrtf(v + EPSv)*bng[c] + bnb[c];
    out[i] = fmaxf(o, 0.f);
}

// ---------------- host launcher ----------------
extern "C" void kernel_launch(void* const* d_in, const int* in_sizes, int n_in,
                              void* d_out, int out_size)
{
    const float* cur      = (const float*)d_in[0];
    const float* hist0    = (const float*)d_in[1];
    const float* hist1    = (const float*)d_in[2];
    const float* offset_w = (const float*)d_in[3];
    const float* offset_b = (const float*)d_in[4];
    const float* deform_w = (const float*)d_in[5];
    const float* ca_w1    = (const float*)d_in[6];
    const float* ca_w2    = (const float*)d_in[7];
    const float* out_w    = (const float*)d_in[8];
    const float* gn_g     = (const float*)d_in[9];
    const float* gn_b     = (const float*)d_in[10];
    const float* fuse_w   = (const float*)d_in[11];
    const float* bn_g     = (const float*)d_in[12];
    const float* bn_b     = (const float*)d_in[13];
    float* out = (float*)d_out;

    float *p_y;
    float2 *p_stat;
    __half *p_w1h, *p_w1l, *p_w2h, *p_w2l, *p_padT;
    cudaGetSymbolAddress((void**)&p_y, g_y);
    cudaGetSymbolAddress((void**)&p_stat, g_stat);
    cudaGetSymbolAddress((void**)&p_w1h, g_w1h);
    cudaGetSymbolAddress((void**)&p_w1l, g_w1l);
    cudaGetSymbolAddress((void**)&p_w2h, g_w2h);
    cudaGetSymbolAddress((void**)&p_w2l, g_w2l);
    cudaGetSymbolAddress((void**)&p_padT, g_padT);

    cudaFuncSetAttribute(conv3x3_mma_kernel,
                         cudaFuncAttributeMaxDynamicSharedMemorySize, CONV_SMEM);

    dim3 tGrid(313, 8, 3), tBlock(32, 8);
    dim3 fuseGrid(313, 8, 2);
    dim3 gnGrid(313, 8);
    dim3 offGrid(79, 2, 2);
    dim3 convGrid(80, 4, 2);
    dim3 conv3Grid(80, 4, 1);
    const int NW = Cc*Cc*9;
    const int PREP_TOT = 2*NW + 64*512 + Tt*Cc + 2*CH*Cc;

    split_xT_kernel<<<tGrid, tBlock>>>(cur, hist0, hist1);                    // 0
    prep_w_kernel<<<(PREP_TOT + 255)/256, 256>>>(out_w, fuse_w, offset_w, deform_w); // 1
    offset_mma_kernel<<<offGrid, 256>>>(offset_b);                            // 2
    deform_kernel<<<dim3(1250, 2), 256>>>();                                  // 3 (profiled)
    attn_kernel<<<1, Cc>>>(ca_w1, ca_w2);                                     // 4
    fuse1T_kernel<<<fuseGrid, tBlock>>>(cur);                                 // 5
    conv3x3_mma_kernel<<<convGrid, 256, CONV_SMEM>>>(p_w1h, p_w1l, p_padT, p_y, p_stat); // 6
    gn_norm_comb_kernel<<<gnGrid, tBlock>>>(gn_g, gn_b);                      // 7
    conv3x3_mma_kernel<<<conv3Grid, 256, CONV_SMEM>>>(p_w2h, p_w2l, p_padT, p_y, p_stat + 2*Cc); // 8
    bn_norm_kernel<<<Cc*Pp/256, 256>>>(bn_g, bn_b, out);                      // 9
}

// round 16
// speedup vs baseline: 1.4871x; 1.2769x over previous
#include <cuda_runtime.h>
#include <cuda_fp16.h>
#include <math.h>
#include <stdint.h>

#define Cc   256
#define Hh   100
#define Ww   100
#define Pp   10000
#define Tt   25
#define MIDc 32
#define GRP  8
#define EPSv 1e-5f

#define PW    102
#define CH    10752
#define NB    10200
#define WSCALE 64.f
#define WINV   0.015625f

// ---------------- scratch ----------------
__device__ __align__(16) __half g_xT[3*Pp*Cc];      // cur,h0,h1 pixel-major fp16
__device__ __align__(16) __half g_padT[2*CH*Cc];    // conv inputs (padded, pixel-major)
__device__ __align__(16) __half g_owh[64*512];      // offset weights x64 (fp16)
__device__ __align__(16) __half g_w1h[9*Cc*Cc];     // out_w x64 [tap][oc][ic]
__device__ __align__(16) __half g_w2h[9*Cc*Cc];     // fuse_w x64
__device__ float  g_offA[2*50*Pp];
__device__ float  g_offB[2*50*Pp];
__device__ float  g_dwT[Tt*Cc];
__device__ float  g_aligned[2*Cc*Pp];
__device__ float  g_y[2*Cc*Pp];
__device__ float  g_red[2][2*Cc];                   // RAW SUMS (atomic accumulated)
__device__ float  g_attn[2][Cc];
__device__ float2 g_stat[3*Cc];

// ---------------- helpers ----------------
__device__ __forceinline__ uint32_t smem_u32(const void* p) {
    uint32_t a;
    asm("{ .reg .u64 t; cvta.to.shared.u64 t, %1; cvt.u32.u64 %0, t; }" : "=r"(a) : "l"(p));
    return a;
}
__device__ __forceinline__ void ldsm4(uint32_t* r, uint32_t addr) {
    asm volatile("ldmatrix.sync.aligned.m8n8.x4.shared.b16 {%0,%1,%2,%3}, [%4];"
        : "=r"(r[0]), "=r"(r[1]), "=r"(r[2]), "=r"(r[3]) : "r"(addr));
}
__device__ __forceinline__ void mma16816h(float* c, uint32_t a0, uint32_t a1,
                                          uint32_t a2, uint32_t a3,
                                          uint32_t b0, uint32_t b1)
{
    asm volatile(
        "mma.sync.aligned.m16n8k16.row.col.f32.f16.f16.f32 "
        "{%0,%1,%2,%3}, {%4,%5,%6,%7}, {%8,%9}, {%0,%1,%2,%3};"
        : "+f"(c[0]), "+f"(c[1]), "+f"(c[2]), "+f"(c[3])
        : "r"(a0), "r"(a1), "r"(a2), "r"(a3), "r"(b0), "r"(b1));
}
__device__ __forceinline__ void cp16(uint32_t dst, const void* src) {
    asm volatile("cp.async.cg.shared.global [%0], [%1], 16;" :: "r"(dst), "l"(src));
}
#define CP_COMMIT() asm volatile("cp.async.commit_group;" ::: "memory")
#define CP_WAIT0()  asm volatile("cp.async.wait_group 0;" ::: "memory")

// ------- prep: weight converts + dwT + zero stats/red + zero pad border ---------
__global__ void prep_w_kernel(const float* __restrict__ w1,
                              const float* __restrict__ w2,
                              const float* __restrict__ ow,
                              const float* __restrict__ dw)
{
    const int n = Cc*Cc*9;
    int i = blockIdx.x*256 + threadIdx.x;
    if (i < 3*Cc) g_stat[i] = make_float2(0.f, 0.f);
    if (i < 4*Cc) ((float*)g_red)[i] = 0.f;
    if (i < 2*n) {
        int which = (i >= n);
        int ii = which ? i - n : i;
        float v = (which ? w2[ii] : w1[ii]) * WSCALE;
        int oc = ii / (Cc*9);
        int rem = ii % (Cc*9);
        int ic = rem / 9;
        int t  = rem % 9;
        int dst = (t*Cc + oc)*Cc + ic;
        if (which) g_w2h[dst] = __float2half_rn(v);
        else       g_w1h[dst] = __float2half_rn(v);
        return;
    }
    int j = i - 2*n;
    if (j < 64*512) {
        int row = j >> 9;
        float v = (row < 50) ? ow[j]*WSCALE : 0.f;
        g_owh[j] = __float2half_rn(v);
        return;
    }
    int k = j - 64*512;
    if (k < Tt*Cc) {
        int t = k / Cc, c = k % Cc;
        g_dwT[k] = dw[c*Tt + t];
        return;
    }
    int z = k - Tt*Cc;
    if (z < 2*CH*Cc) {
        int buf = z / (CH*Cc);
        int rem = z - buf*CH*Cc;
        int gp = rem >> 8, c = rem & 255;
        int y = gp / PW, x = gp - y*PW;
        bool interior = (y >= 1 && y <= 100 && x >= 1 && x <= 100);
        if (!interior) g_padT[buf*CH*Cc + gp*Cc + c] = __float2half(0.f);
    }
}

// ------- transpose to fp16 pixel-major ----------------
__global__ void split_xT_kernel(const float* __restrict__ cur,
                                const float* __restrict__ h0,
                                const float* __restrict__ h1)
{
    __shared__ float tile[32][33];
    int z = blockIdx.z;
    const float* src = (z == 0) ? cur : (z == 1) ? h0 : h1;
    __half* dst = g_xT + z*Pp*Cc;
    int p0 = blockIdx.x*32, c0 = blockIdx.y*32;
    int tx = threadIdx.x, ty = threadIdx.y;
    #pragma unroll
    for (int i = ty; i < 32; i += 8) {
        int p = p0 + tx;
        tile[i][tx] = (p < Pp) ? src[(c0+i)*Pp + p] : 0.f;
    }
    __syncthreads();
    #pragma unroll
    for (int i = ty; i < 32; i += 8) {
        int p = p0 + i;
        if (p < Pp) dst[p*Cc + c0 + tx] = __float2half(tile[tx][i]);
    }
}

// ---------------- offset 1x1 conv: fp16 1-pass, K-split(y), hist(z) -------------
__global__ void __launch_bounds__(256)
offset_mma_kernel(const float* __restrict__ bias)
{
    __shared__ __align__(16) __half s_ah[64][24];
    __shared__ __align__(16) __half s_b[128][24];
    int p0 = blockIdx.x*128;
    int ks = blockIdx.y;
    int h  = blockIdx.z;
    const __half* x = (ks == 0) ? g_xT : (g_xT + (1+h)*Pp*Cc);
    float* outp = (ks == 0) ? (g_offA + h*50*Pp) : (g_offB + h*50*Pp);
    int kbase = ks*256;
    int tid = threadIdx.x;
    int wid = tid >> 5, lane = tid & 31;
    int wm = wid & 1, wn = wid >> 1;
    int k0 = (lane & 3)*2, grp = lane >> 2;

    float acc[2][4][4];
    #pragma unroll
    for (int mt = 0; mt < 2; mt++)
        #pragma unroll
        for (int nt = 0; nt < 4; nt++)
            #pragma unroll
            for (int r = 0; r < 4; r++) acc[mt][nt][r] = 0.f;

    for (int kk = 0; kk < 256; kk += 16) {
        __syncthreads();
        if (tid < 128) {
            int m = tid >> 1, half = tid & 1;
            uint4 v = *(const uint4*)&g_owh[m*512 + kbase + kk + half*8];
            *(uint4*)&s_ah[m][half*8] = v;
        }
        {
            int pos = tid >> 1, half = tid & 1;
            int p = p0 + pos;
            uint4 v = make_uint4(0u,0u,0u,0u);
            if (p < Pp) v = *(const uint4*)&x[p*Cc + kk + half*8];
            *(uint4*)&s_b[pos][half*8] = v;
        }
        __syncthreads();

        uint32_t ah[2][4], bf[4][2];
        #pragma unroll
        for (int mt = 0; mt < 2; mt++) {
            int m = wm*32 + mt*16 + grp;
            ah[mt][0] = *(const uint32_t*)&s_ah[m][k0];
            ah[mt][1] = *(const uint32_t*)&s_ah[m+8][k0];
            ah[mt][2] = *(const uint32_t*)&s_ah[m][k0+8];
            ah[mt][3] = *(const uint32_t*)&s_ah[m+8][k0+8];
        }
        #pragma unroll
        for (int nt = 0; nt < 4; nt++) {
            int n = wn*32 + nt*8 + grp;
            bf[nt][0] = *(const uint32_t*)&s_b[n][k0];
            bf[nt][1] = *(const uint32_t*)&s_b[n][k0+8];
        }
        #pragma unroll
        for (int mt = 0; mt < 2; mt++)
            #pragma unroll
            for (int nt = 0; nt < 4; nt++)
                mma16816h(acc[mt][nt], ah[mt][0], ah[mt][1], ah[mt][2], ah[mt][3], bf[nt][0], bf[nt][1]);
    }
    #pragma unroll
    for (int mt = 0; mt < 2; mt++)
        #pragma unroll
        for (int nt = 0; nt < 4; nt++)
            #pragma unroll
            for (int r = 0; r < 4; r++) {
                int j = wm*32 + mt*16 + grp + ((r >= 2) ? 8 : 0);
                int p = p0 + wn*32 + nt*8 + (lane & 3)*2 + (r & 1);
                if (j < 50 && p < Pp) {
                    float v = acc[mt][nt][r] * WINV;
                    if (ks == 0) v += bias[j];
                    outp[j*Pp + p] = v;
                }
            }
}

// ------ deformable depthwise conv + fused per-channel reductions ---------------
__global__ void deform_kernel()
{
    __shared__ float s_dw[Tt*Cc];
    __shared__ int   s_base[8][Tt][4];
    __shared__ float s_wt[8][Tt][4];
    __shared__ float s_t1[8][Cc];
    __shared__ float s_t2[8][Cc];
    int h = blockIdx.y;
    const __half* histT = g_xT + (1+h)*Pp*Cc;
    const float* offA = g_offA + h*50*Pp;
    const float* offB = g_offB + h*50*Pp;
    float* alignedp = g_aligned + h*Cc*Pp;
    int p0 = blockIdx.x*8;
    int tid = threadIdx.x;
    for (int i = tid; i < Tt*Cc; i += 256) s_dw[i] = g_dwT[i];
    if (tid < 200) {
        int pi = tid / 25, t = tid % 25;
        int p = p0 + pi;
        int y = p / Ww, x = p % Ww;
        float dy = offA[(2*t)*Pp + p]   + offB[(2*t)*Pp + p];
        float dx = offA[(2*t+1)*Pp + p] + offB[(2*t+1)*Pp + p];
        float ys = (float)(y + t/5 - 2) + dy;
        float xs = (float)(x + t%5 - 2) + dx;
        float y0 = floorf(ys), x0 = floorf(xs);
        float wy = ys - y0, wx = xs - x0;
        float cy[2] = {y0, y0+1.f}, cx[2] = {x0, x0+1.f};
        float wyv[2] = {1.f-wy, wy}, wxv[2] = {1.f-wx, wx};
        #pragma unroll
        for (int a = 0; a < 2; a++)
        #pragma unroll
        for (int bq = 0; bq < 2; bq++) {
            int k = a*2 + bq;
            bool valid = (cy[a] >= 0.f) && (cy[a] <= 99.f) &&
                         (cx[bq] >= 0.f) && (cx[bq] <= 99.f);
            int yi = (int)fminf(fmaxf(cy[a], 0.f), 99.f);
            int xi = (int)fminf(fmaxf(cx[bq], 0.f), 99.f);
            s_base[pi][t][k] = (yi*Ww + xi)*Cc;
            s_wt[pi][t][k]   = valid ? wyv[a]*wxv[bq] : 0.f;
        }
    }
    __syncthreads();
    int pi = tid >> 5;
    int cq = (tid & 31) << 3;
    int p = p0 + pi;
    float acc[8];
    #pragma unroll
    for (int i = 0; i < 8; i++) acc[i] = 0.f;
    #pragma unroll 5
    for (int t = 0; t < Tt; t++) {
        float sv[8];
        #pragma unroll
        for (int i = 0; i < 8; i++) sv[i] = 0.f;
        #pragma unroll
        for (int k = 0; k < 4; k++) {
            float wv = s_wt[pi][t][k];
            uint4 raw = *(const uint4*)(histT + s_base[pi][t][k] + cq);
            const __half2* hp = (const __half2*)&raw;
            #pragma unroll
            for (int q = 0; q < 4; q++) {
                float2 f = __half22float2(hp[q]);
                sv[2*q]   += wv*f.x;
                sv[2*q+1] += wv*f.y;
            }
        }
        const float4* dwp = (const float4*)&s_dw[t*Cc + cq];
        float4 d0 = dwp[0], d1 = dwp[1];
        acc[0] += d0.x*sv[0]; acc[1] += d0.y*sv[1];
        acc[2] += d0.z*sv[2]; acc[3] += d0.w*sv[3];
        acc[4] += d1.x*sv[4]; acc[5] += d1.y*sv[5];
        acc[6] += d1.z*sv[6]; acc[7] += d1.w*sv[7];
    }
    #pragma unroll
    for (int i = 0; i < 8; i++)
        alignedp[(cq+i)*Pp + p] = acc[i];
    {
        uint4 rawc = *(const uint4*)(g_xT + p*Cc + cq);
        uint4 rawh = *(const uint4*)(histT + p*Cc + cq);
        const __half2* hc = (const __half2*)&rawc;
        const __half2* hh = (const __half2*)&rawh;
        float t1[8], t2[8];
        #pragma unroll
        for (int q = 0; q < 4; q++) {
            float2 fc = __half22float2(hc[q]);
            float2 fh = __half22float2(hh[q]);
            t1[2*q]   = fc.x - acc[2*q];
            t1[2*q+1] = fc.y - acc[2*q+1];
            t2[2*q]   = fabsf(fc.x - fh.x);
            t2[2*q+1] = fabsf(fc.y - fh.y);
        }
        *(float4*)&s_t1[pi][cq]     = make_float4(t1[0], t1[1], t1[2], t1[3]);
        *(float4*)&s_t1[pi][cq+4]   = make_float4(t1[4], t1[5], t1[6], t1[7]);
        *(float4*)&s_t2[pi][cq]     = make_float4(t2[0], t2[1], t2[2], t2[3]);
        *(float4*)&s_t2[pi][cq+4]   = make_float4(t2[4], t2[5], t2[6], t2[7]);
    }
    __syncthreads();
    {
        int c = tid;
        float s1 = 0.f, s2 = 0.f;
        #pragma unroll
        for (int q = 0; q < 8; q++) { s1 += s_t1[q][c]; s2 += s_t2[q][c]; }
        atomicAdd(&g_red[h][c], s1);
        atomicAdd(&g_red[h][Cc + c], s2);
    }
}

// ---------------- channel attention for BOTH hists ------------------------------
__global__ void attn_kernel(const float* __restrict__ w1,
                            const float* __restrict__ w2)
{
    __shared__ float s_pool[Cc];
    __shared__ float s_hid[MIDc];
    int tid = threadIdx.x;
    const float inv = 1.f/(float)Pp;
    for (int h = 0; h < 2; h++) {
        s_pool[tid] = g_red[h][tid] * inv;
        __syncthreads();
        if (tid < MIDc) {
            float a = 0.f;
            #pragma unroll 8
            for (int c2 = 0; c2 < Cc; c2++) a += w1[tid*Cc + c2]*s_pool[c2];
            s_hid[tid] = fmaxf(a, 0.f);
        }
        __syncthreads();
        float a = 0.f;
        #pragma unroll
        for (int m = 0; m < MIDc; m++) a += w2[tid*MIDc + m]*s_hid[m];
        g_attn[h][tid] = 1.f/(1.f + expf(-a));
        __syncthreads();
    }
}

// ---------------- fused = cur + aligned*attn -> padded fp16 ---------------------
__global__ void fuse1T_kernel(const float* __restrict__ cur)
{
    __shared__ float tc[32][33], ta[32][33];
    int h = blockIdx.z;
    const float* alignedp = g_aligned + h*Cc*Pp;
    __half* dst = g_padT + h*CH*Cc;
    int p0 = blockIdx.x*32, c0 = blockIdx.y*32;
    int tx = threadIdx.x, ty = threadIdx.y;
    #pragma unroll
    for (int i = ty; i < 32; i += 8) {
        int p = p0 + tx;
        tc[i][tx] = (p < Pp) ? cur[(c0+i)*Pp + p] : 0.f;
        ta[i][tx] = (p < Pp) ? alignedp[(c0+i)*Pp + p] : 0.f;
    }
    __syncthreads();
    #pragma unroll
    for (int i = ty; i < 32; i += 8) {
        int p = p0 + i;
        if (p < Pp) {
            int c = c0 + tx;
            float f = tc[tx][i] + ta[tx][i]*g_attn[h][c];
            int y = p / Ww, x = p - y*Ww;
            int gp = (y+1)*PW + x + 1;
            dst[gp*Cc + c] = __float2half(f);
        }
    }
}

// ---------------- conv3x3: fp16 1-pass, M=64 tile, occ 3, cp.async --------------
#define SA_ELE (9*64*16)                 // 9216 halfs
#define STAGE_ELE (SA_ELE + 396*16)      // 15552 halfs
#define STAGE_BYTES (STAGE_ELE*2)        // 31104
#define CONV_SMEM (2*STAGE_BYTES)        // 62208

__global__ void __launch_bounds__(256, 3)
conv3x3_mma_kernel(const __half* __restrict__ wh,
                   const __half* __restrict__ in_base,
                   float* __restrict__ out_base,
                   float2* __restrict__ stat_base)
{
    extern __shared__ __half sm2[];
    uint32_t s0 = smem_u32(sm2);

    int z = blockIdx.z;
    const __half* inp = in_base + z*CH*Cc;
    float* out = out_base + z*Cc*Pp;
    float2* stat = stat_base + z*Cc;

    int b0  = blockIdx.x*128;
    int oc0 = blockIdx.y*64;
    int tid = threadIdx.x;
    int wid = tid >> 5, lane = tid & 31;
    int wm = wid & 1, wn = wid >> 1;

    float acc[2][4][4];
    #pragma unroll
    for (int mt = 0; mt < 2; mt++)
        #pragma unroll
        for (int nt = 0; nt < 4; nt++)
            #pragma unroll
            for (int r = 0; r < 4; r++) acc[mt][nt][r] = 0.f;

    int a_lrow = lane & 15;
    int a_ksel = (lane >> 4) & 1;
    int b_tile = lane >> 3;
    int b_r    = lane & 7;
    int b_ntof = (b_tile >> 1)*8;
    int b_ks   = b_tile & 1;

    auto issue = [&](int ic0, int buf) {
        uint32_t base = s0 + buf*STAGE_BYTES;
        uint32_t sbh = base;
        uint32_t sbb = base + SA_ELE*2;
        for (int i = tid; i < 1152; i += 256) {
            int row = i >> 1, half = i & 1;
            int t = row >> 6, m = row & 63;
            int src = (t*Cc + oc0 + m)*Cc + ic0 + half*8;
            cp16(sbh + (uint32_t)((row*16 + half*8)*2), wh + src);
        }
        for (int i = tid; i < 792; i += 256) {
            int row = i >> 1, half = i & 1;
            int prow = row / 132;
            int col  = row - prow*132;
            int src = (b0 + prow*PW + col)*Cc + ic0 + half*8;
            cp16(sbb + (uint32_t)((row*16 + half*8)*2), inp + src);
        }
        CP_COMMIT();
    };

    issue(0, 0);
    for (int s = 0; s < 16; s++) {
        CP_WAIT0();
        __syncthreads();
        if (s < 15) issue((s+1)*16, (s+1) & 1);

        uint32_t base = s0 + (s & 1)*STAGE_BYTES;
        uint32_t sa_h = base;
        uint32_t sb   = base + SA_ELE*2;

        #pragma unroll
        for (int t = 0; t < 9; t++) {
            uint32_t ah[2][4];
            #pragma unroll
            for (int mt = 0; mt < 2; mt++) {
                uint32_t aoff = (uint32_t)(((t*64 + wm*32 + mt*16 + a_lrow)*16 + a_ksel*8)*2);
                ldsm4(ah[mt], sa_h + aoff);
            }
            int posb = (t/3)*132 + (t%3) + wn*32;
            uint32_t bf[4][2];
            #pragma unroll
            for (int np = 0; np < 2; np++) {
                int row = posb + np*16 + b_ntof + b_r;
                uint32_t addr = sb + (uint32_t)((row*16 + b_ks*8)*2);
                uint32_t rr[4];
                ldsm4(rr, addr);
                bf[2*np][0] = rr[0]; bf[2*np][1] = rr[1];
                bf[2*np+1][0] = rr[2]; bf[2*np+1][1] = rr[3];
            }
            #pragma unroll
            for (int mt = 0; mt < 2; mt++)
                #pragma unroll
                for (int nt = 0; nt < 4; nt++)
                    mma16816h(acc[mt][nt], ah[mt][0], ah[mt][1], ah[mt][2], ah[mt][3], bf[nt][0], bf[nt][1]);
        }
        __syncthreads();
    }
    const unsigned FULL = 0xFFFFFFFFu;
    #pragma unroll
    for (int mt = 0; mt < 2; mt++) {
        #pragma unroll
        for (int rh = 0; rh < 2; rh++) {
            int m = oc0 + wm*32 + mt*16 + (lane >> 2) + rh*8;
            float s = 0.f, ss = 0.f;
            #pragma unroll
            for (int nt = 0; nt < 4; nt++) {
                #pragma unroll
                for (int rl = 0; rl < 2; rl++) {
                    float val = acc[mt][nt][rh*2 + rl] * WINV;
                    int n = wn*32 + nt*8 + (lane & 3)*2 + rl;
                    int b = b0 + n;
                    int y = b / PW;
                    int x = b - y*PW;
                    if (b < NB && x < Ww) {
                        out[m*Pp + y*Ww + x] = val;
                        s += val; ss += val*val;
                    }
                }
            }
            s  += __shfl_down_sync(FULL, s, 2);
            s  += __shfl_down_sync(FULL, s, 1);
            ss += __shfl_down_sync(FULL, ss, 2);
            ss += __shfl_down_sync(FULL, ss, 1);
            if ((lane & 3) == 0) {
                atomicAdd(&stat[m].x, s);
                atomicAdd(&stat[m].y, ss);
            }
        }
    }
}

// ---- GN (inline group-stat fold) + weighted fuse -> conv3 input ----------------
__global__ void gn_norm_comb_kernel(const float* __restrict__ gng,
                                    const float* __restrict__ gnb)
{
    __shared__ float tY0[32][33], tY1[32][33];
    __shared__ float s_ms[2][2];
    int p0 = blockIdx.x*32, c0 = blockIdx.y*32;
    int tx = threadIdx.x, ty = threadIdx.y;
    int ltid = ty*32 + tx;
    if (ltid < 64) {
        int h = ltid >> 5, lane = ltid & 31;
        float2 v = g_stat[h*Cc + c0 + lane];
        float s = v.x, ss = v.y;
        #pragma unroll
        for (int o = 16; o > 0; o >>= 1) {
            s  += __shfl_down_sync(0xFFFFFFFFu, s, o);
            ss += __shfl_down_sync(0xFFFFFFFFu, ss, o);
        }
        if (lane == 0) {
            const float N = 32.f*(float)Pp;
            float m = s/N;
            s_ms[h][0] = m;
            s_ms[h][1] = ss/N - m*m;
        }
    }
    #pragma unroll
    for (int i = ty; i < 32; i += 8) {
        int p = p0 + tx;
        tY0[i][tx] = (p < Pp) ? g_y[(c0+i)*Pp + p] : 0.f;
        tY1[i][tx] = (p < Pp) ? g_y[Cc*Pp + (c0+i)*Pp + p] : 0.f;
    }
    __syncthreads();
    int c = c0 + tx;
    const float inv = 1.f/(float)Pp;
    float wgt0 = 1.f/(1.f + expf(g_red[0][Cc + c]*inv));
    float wgt1 = 1.f/(1.f + expf(g_red[1][Cc + c]*inv));
    float winv = 1.f/(wgt0 + wgt1 + 1e-6f);
    float gg = gng[c], gb = gnb[c];
    float m0 = s_ms[0][0], r0 = rsqrtf(s_ms[0][1] + EPSv);
    float m1 = s_ms[1][0], r1 = rsqrtf(s_ms[1][1] + EPSv);
    #pragma unroll
    for (int i = ty; i < 32; i += 8) {
        int p = p0 + i;
        if (p < Pp) {
            float h0 = fmaxf((tY0[tx][i] - m0)*r0*gg + gb, 0.f);
            float h1 = fmaxf((tY1[tx][i] - m1)*r1*gg + gb, 0.f);
            float f = (h0*wgt0 + h1*wgt1) * winv;
            int y = p / Ww, x = p - y*Ww;
            int gp = (y+1)*PW + x + 1;
            g_padT[gp*Cc + c] = __float2half(f);
        }
    }
}

// ---------------- BN normalize + relu -> output ----------------
__global__ void bn_norm_kernel(const float* __restrict__ bng,
                               const float* __restrict__ bnb,
                               float* __restrict__ out)
{
    int i = blockIdx.x*256 + threadIdx.x;
    int c = i / Pp;
    float2 st = g_stat[2*Cc + c];
    float m = st.x * (1.f/(float)Pp);
    float v = st.y * (1.f/(float)Pp) - m*m;
    float o = (g_y[i] - m)*rsqrtf(v + EPSv)*bng[c] + bnb[c];
    out[i] = fmaxf(o, 0.f);
}

// ---------------- host launcher ----------------
extern "C" void kernel_launch(void* const* d_in, const int* in_sizes, int n_in,
                              void* d_out, int out_size)
{
    const float* cur      = (const float*)d_in[0];
    const float* hist0    = (const float*)d_in[1];
    const float* hist1    = (const float*)d_in[2];
    const float* offset_w = (const float*)d_in[3];
    const float* offset_b = (const float*)d_in[4];
    const float* deform_w = (const float*)d_in[5];
    const float* ca_w1    = (const float*)d_in[6];
    const float* ca_w2    = (const float*)d_in[7];
    const float* out_w    = (const float*)d_in[8];
    const float* gn_g     = (const float*)d_in[9];
    const float* gn_b     = (const float*)d_in[10];
    const float* fuse_w   = (const float*)d_in[11];
    const float* bn_g     = (const float*)d_in[12];
    const float* bn_b     = (const float*)d_in[13];
    float* out = (float*)d_out;

    float *p_y;
    float2 *p_stat;
    __half *p_w1h, *p_w2h, *p_padT;
    cudaGetSymbolAddress((void**)&p_y, g_y);
    cudaGetSymbolAddress((void**)&p_stat, g_stat);
    cudaGetSymbolAddress((void**)&p_w1h, g_w1h);
    cudaGetSymbolAddress((void**)&p_w2h, g_w2h);
    cudaGetSymbolAddress((void**)&p_padT, g_padT);

    cudaFuncSetAttribute(conv3x3_mma_kernel,
                         cudaFuncAttributeMaxDynamicSharedMemorySize, CONV_SMEM);

    dim3 tGrid(313, 8, 3), tBlock(32, 8);
    dim3 fuseGrid(313, 8, 2);
    dim3 gnGrid(313, 8);
    dim3 offGrid(79, 2, 2);
    dim3 convGrid(80, 4, 2);
    dim3 conv3Grid(80, 4, 1);
    const int NW = Cc*Cc*9;
    const int PREP_TOT = 2*NW + 64*512 + Tt*Cc + 2*CH*Cc;

    split_xT_kernel<<<tGrid, tBlock>>>(cur, hist0, hist1);                    // 0
    prep_w_kernel<<<(PREP_TOT + 255)/256, 256>>>(out_w, fuse_w, offset_w, deform_w); // 1
    offset_mma_kernel<<<offGrid, 256>>>(offset_b);                            // 2
    deform_kernel<<<dim3(1250, 2), 256>>>();                                  // 3 (profiled)
    attn_kernel<<<1, Cc>>>(ca_w1, ca_w2);                                     // 4
    fuse1T_kernel<<<fuseGrid, tBlock>>>(cur);                                 // 5
    conv3x3_mma_kernel<<<convGrid, 256, CONV_SMEM>>>(p_w1h, p_padT, p_y, p_stat); // 6
    gn_norm_comb_kernel<<<gnGrid, tBlock>>>(gn_g, gn_b);                      // 7
    conv3x3_mma_kernel<<<conv3Grid, 256, CONV_SMEM>>>(p_w2h, p_padT, p_y, p_stat + 2*Cc); // 8
    bn_norm_kernel<<<Cc*Pp/256, 256>>>(bn_g, bn_b, out);                      // 9
}

// round 17
// speedup vs baseline: 1.6079x; 1.0813x over previous
#include <cuda_runtime.h>
#include <cuda_fp16.h>
#include <math.h>
#include <stdint.h>

#define Cc   256
#define Hh   100
#define Ww   100
#define Pp   10000
#define Tt   25
#define MIDc 32
#define GRP  8
#define EPSv 1e-5f

#define PW    102
#define CH    10752
#define NB    10200
#define WSCALE 64.f
#define WINV   0.015625f

// ---------------- scratch ----------------
__device__ __align__(16) __half g_xT[3*Pp*Cc];      // cur,h0,h1 pixel-major fp16
__device__ __align__(16) __half g_padT[2*CH*Cc];    // conv inputs (padded, pixel-major)
__device__ __align__(16) __half g_alignedH[2*Pp*Cc];// aligned, fp16 pixel-major
__device__ __align__(16) __half g_owh[64*512];
__device__ __align__(16) __half g_w1h[9*Cc*Cc];
__device__ __align__(16) __half g_w2h[9*Cc*Cc];
__device__ float  g_offA[2*50*Pp];
__device__ float  g_offB[2*50*Pp];
__device__ float  g_dwT[Tt*Cc];
__device__ float  g_y[2*Cc*Pp];
__device__ float  g_red[2][2*Cc];                   // RAW SUMS (atomic accumulated)
__device__ float  g_attn[2][Cc];
__device__ float2 g_stat[3*Cc];

// ---------------- helpers ----------------
__device__ __forceinline__ uint32_t smem_u32(const void* p) {
    uint32_t a;
    asm("{ .reg .u64 t; cvta.to.shared.u64 t, %1; cvt.u32.u64 %0, t; }" : "=r"(a) : "l"(p));
    return a;
}
__device__ __forceinline__ void ldsm4(uint32_t* r, uint32_t addr) {
    asm volatile("ldmatrix.sync.aligned.m8n8.x4.shared.b16 {%0,%1,%2,%3}, [%4];"
        : "=r"(r[0]), "=r"(r[1]), "=r"(r[2]), "=r"(r[3]) : "r"(addr));
}
__device__ __forceinline__ void mma16816h(float* c, uint32_t a0, uint32_t a1,
                                          uint32_t a2, uint32_t a3,
                                          uint32_t b0, uint32_t b1)
{
    asm volatile(
        "mma.sync.aligned.m16n8k16.row.col.f32.f16.f16.f32 "
        "{%0,%1,%2,%3}, {%4,%5,%6,%7}, {%8,%9}, {%0,%1,%2,%3};"
        : "+f"(c[0]), "+f"(c[1]), "+f"(c[2]), "+f"(c[3])
        : "r"(a0), "r"(a1), "r"(a2), "r"(a3), "r"(b0), "r"(b1));
}
__device__ __forceinline__ void cp16(uint32_t dst, const void* src) {
    asm volatile("cp.async.cg.shared.global [%0], [%1], 16;" :: "r"(dst), "l"(src));
}
#define CP_COMMIT() asm volatile("cp.async.commit_group;" ::: "memory")
#define CP_WAIT0()  asm volatile("cp.async.wait_group 0;" ::: "memory")

// ------- prep: weight converts + dwT + zero stats/red + zero pad border ---------
__global__ void prep_w_kernel(const float* __restrict__ w1,
                              const float* __restrict__ w2,
                              const float* __restrict__ ow,
                              const float* __restrict__ dw)
{
    const int n = Cc*Cc*9;
    int i = blockIdx.x*256 + threadIdx.x;
    if (i < 3*Cc) g_stat[i] = make_float2(0.f, 0.f);
    if (i < 4*Cc) ((float*)g_red)[i] = 0.f;
    if (i < 2*n) {
        int which = (i >= n);
        int ii = which ? i - n : i;
        float v = (which ? w2[ii] : w1[ii]) * WSCALE;
        int oc = ii / (Cc*9);
        int rem = ii % (Cc*9);
        int ic = rem / 9;
        int t  = rem % 9;
        int dst = (t*Cc + oc)*Cc + ic;
        if (which) g_w2h[dst] = __float2half_rn(v);
        else       g_w1h[dst] = __float2half_rn(v);
        return;
    }
    int j = i - 2*n;
    if (j < 64*512) {
        int row = j >> 9;
        float v = (row < 50) ? ow[j]*WSCALE : 0.f;
        g_owh[j] = __float2half_rn(v);
        return;
    }
    int k = j - 64*512;
    if (k < Tt*Cc) {
        int t = k / Cc, c = k % Cc;
        g_dwT[k] = dw[c*Tt + t];
        return;
    }
    int z = k - Tt*Cc;
    if (z < 2*CH*Cc) {
        int buf = z / (CH*Cc);
        int rem = z - buf*CH*Cc;
        int gp = rem >> 8, c = rem & 255;
        int y = gp / PW, x = gp - y*PW;
        bool interior = (y >= 1 && y <= 100 && x >= 1 && x <= 100);
        if (!interior) g_padT[buf*CH*Cc + gp*Cc + c] = __float2half(0.f);
    }
}

// ------- transpose to fp16 pixel-major ----------------
__global__ void split_xT_kernel(const float* __restrict__ cur,
                                const float* __restrict__ h0,
                                const float* __restrict__ h1)
{
    __shared__ float tile[32][33];
    int z = blockIdx.z;
    const float* src = (z == 0) ? cur : (z == 1) ? h0 : h1;
    __half* dst = g_xT + z*Pp*Cc;
    int p0 = blockIdx.x*32, c0 = blockIdx.y*32;
    int tx = threadIdx.x, ty = threadIdx.y;
    #pragma unroll
    for (int i = ty; i < 32; i += 8) {
        int p = p0 + tx;
        tile[i][tx] = (p < Pp) ? src[(c0+i)*Pp + p] : 0.f;
    }
    __syncthreads();
    #pragma unroll
    for (int i = ty; i < 32; i += 8) {
        int p = p0 + i;
        if (p < Pp) dst[p*Cc + c0 + tx] = __float2half(tile[tx][i]);
    }
}

// ---------------- offset 1x1 conv: fp16 1-pass, K-split(y), hist(z) -------------
__global__ void __launch_bounds__(256)
offset_mma_kernel(const float* __restrict__ bias)
{
    __shared__ __align__(16) __half s_ah[64][24];
    __shared__ __align__(16) __half s_b[128][24];
    int p0 = blockIdx.x*128;
    int ks = blockIdx.y;
    int h  = blockIdx.z;
    const __half* x = (ks == 0) ? g_xT : (g_xT + (1+h)*Pp*Cc);
    float* outp = (ks == 0) ? (g_offA + h*50*Pp) : (g_offB + h*50*Pp);
    int kbase = ks*256;
    int tid = threadIdx.x;
    int wid = tid >> 5, lane = tid & 31;
    int wm = wid & 1, wn = wid >> 1;
    int k0 = (lane & 3)*2, grp = lane >> 2;

    float acc[2][4][4];
    #pragma unroll
    for (int mt = 0; mt < 2; mt++)
        #pragma unroll
        for (int nt = 0; nt < 4; nt++)
            #pragma unroll
            for (int r = 0; r < 4; r++) acc[mt][nt][r] = 0.f;

    for (int kk = 0; kk < 256; kk += 16) {
        __syncthreads();
        if (tid < 128) {
            int m = tid >> 1, half = tid & 1;
            uint4 v = *(const uint4*)&g_owh[m*512 + kbase + kk + half*8];
            *(uint4*)&s_ah[m][half*8] = v;
        }
        {
            int pos = tid >> 1, half = tid & 1;
            int p = p0 + pos;
            uint4 v = make_uint4(0u,0u,0u,0u);
            if (p < Pp) v = *(const uint4*)&x[p*Cc + kk + half*8];
            *(uint4*)&s_b[pos][half*8] = v;
        }
        __syncthreads();

        uint32_t ah[2][4], bf[4][2];
        #pragma unroll
        for (int mt = 0; mt < 2; mt++) {
            int m = wm*32 + mt*16 + grp;
            ah[mt][0] = *(const uint32_t*)&s_ah[m][k0];
            ah[mt][1] = *(const uint32_t*)&s_ah[m+8][k0];
            ah[mt][2] = *(const uint32_t*)&s_ah[m][k0+8];
            ah[mt][3] = *(const uint32_t*)&s_ah[m+8][k0+8];
        }
        #pragma unroll
        for (int nt = 0; nt < 4; nt++) {
            int n = wn*32 + nt*8 + grp;
            bf[nt][0] = *(const uint32_t*)&s_b[n][k0];
            bf[nt][1] = *(const uint32_t*)&s_b[n][k0+8];
        }
        #pragma unroll
        for (int mt = 0; mt < 2; mt++)
            #pragma unroll
            for (int nt = 0; nt < 4; nt++)
                mma16816h(acc[mt][nt], ah[mt][0], ah[mt][1], ah[mt][2], ah[mt][3], bf[nt][0], bf[nt][1]);
    }
    #pragma unroll
    for (int mt = 0; mt < 2; mt++)
        #pragma unroll
        for (int nt = 0; nt < 4; nt++)
            #pragma unroll
            for (int r = 0; r < 4; r++) {
                int j = wm*32 + mt*16 + grp + ((r >= 2) ? 8 : 0);
                int p = p0 + wn*32 + nt*8 + (lane & 3)*2 + (r & 1);
                if (j < 50 && p < Pp) {
                    float v = acc[mt][nt][r] * WINV;
                    if (ks == 0) v += bias[j];
                    outp[j*Pp + p] = v;
                }
            }
}

// ------ deformable depthwise conv + fused per-channel reductions ---------------
// output: g_alignedH fp16 PIXEL-MAJOR (coalesced 512B warp stores)
__global__ void deform_kernel()
{
    __shared__ float s_dw[Tt*Cc];
    __shared__ int   s_base[8][Tt][4];
    __shared__ float s_wt[8][Tt][4];
    __shared__ float s_t1[8][Cc];
    __shared__ float s_t2[8][Cc];
    int h = blockIdx.y;
    const __half* histT = g_xT + (1+h)*Pp*Cc;
    const float* offA = g_offA + h*50*Pp;
    const float* offB = g_offB + h*50*Pp;
    __half* alignedp = g_alignedH + h*Pp*Cc;
    int p0 = blockIdx.x*8;
    int tid = threadIdx.x;
    for (int i = tid; i < Tt*Cc; i += 256) s_dw[i] = g_dwT[i];
    if (tid < 200) {
        int pi = tid / 25, t = tid % 25;
        int p = p0 + pi;
        int y = p / Ww, x = p % Ww;
        float dy = offA[(2*t)*Pp + p]   + offB[(2*t)*Pp + p];
        float dx = offA[(2*t+1)*Pp + p] + offB[(2*t+1)*Pp + p];
        float ys = (float)(y + t/5 - 2) + dy;
        float xs = (float)(x + t%5 - 2) + dx;
        float y0 = floorf(ys), x0 = floorf(xs);
        float wy = ys - y0, wx = xs - x0;
        float cy[2] = {y0, y0+1.f}, cx[2] = {x0, x0+1.f};
        float wyv[2] = {1.f-wy, wy}, wxv[2] = {1.f-wx, wx};
        #pragma unroll
        for (int a = 0; a < 2; a++)
        #pragma unroll
        for (int bq = 0; bq < 2; bq++) {
            int k = a*2 + bq;
            bool valid = (cy[a] >= 0.f) && (cy[a] <= 99.f) &&
                         (cx[bq] >= 0.f) && (cx[bq] <= 99.f);
            int yi = (int)fminf(fmaxf(cy[a], 0.f), 99.f);
            int xi = (int)fminf(fmaxf(cx[bq], 0.f), 99.f);
            s_base[pi][t][k] = (yi*Ww + xi)*Cc;
            s_wt[pi][t][k]   = valid ? wyv[a]*wxv[bq] : 0.f;
        }
    }
    __syncthreads();
    int pi = tid >> 5;
    int cq = (tid & 31) << 3;
    int p = p0 + pi;
    float acc[8];
    #pragma unroll
    for (int i = 0; i < 8; i++) acc[i] = 0.f;
    #pragma unroll 5
    for (int t = 0; t < Tt; t++) {
        float sv[8];
        #pragma unroll
        for (int i = 0; i < 8; i++) sv[i] = 0.f;
        #pragma unroll
        for (int k = 0; k < 4; k++) {
            float wv = s_wt[pi][t][k];
            uint4 raw = *(const uint4*)(histT + s_base[pi][t][k] + cq);
            const __half2* hp = (const __half2*)&raw;
            #pragma unroll
            for (int q = 0; q < 4; q++) {
                float2 f = __half22float2(hp[q]);
                sv[2*q]   += wv*f.x;
                sv[2*q+1] += wv*f.y;
            }
        }
        const float4* dwp = (const float4*)&s_dw[t*Cc + cq];
        float4 d0 = dwp[0], d1 = dwp[1];
        acc[0] += d0.x*sv[0]; acc[1] += d0.y*sv[1];
        acc[2] += d0.z*sv[2]; acc[3] += d0.w*sv[3];
        acc[4] += d1.x*sv[4]; acc[5] += d1.y*sv[5];
        acc[6] += d1.z*sv[6]; acc[7] += d1.w*sv[7];
    }
    // coalesced fp16 pixel-major store (512B per warp)
    {
        uint4 pk;
        __half2* hp = (__half2*)&pk;
        hp[0] = __floats2half2_rn(acc[0], acc[1]);
        hp[1] = __floats2half2_rn(acc[2], acc[3]);
        hp[2] = __floats2half2_rn(acc[4], acc[5]);
        hp[3] = __floats2half2_rn(acc[6], acc[7]);
        *(uint4*)(alignedp + p*Cc + cq) = pk;
    }
    // fused reduction: sum(cur - aligned), sum |cur - hist| per channel
    {
        uint4 rawc = *(const uint4*)(g_xT + p*Cc + cq);
        uint4 rawh = *(const uint4*)(histT + p*Cc + cq);
        const __half2* hc = (const __half2*)&rawc;
        const __half2* hh = (const __half2*)&rawh;
        float t1[8], t2[8];
        #pragma unroll
        for (int q = 0; q < 4; q++) {
            float2 fc = __half22float2(hc[q]);
            float2 fh = __half22float2(hh[q]);
            t1[2*q]   = fc.x - acc[2*q];
            t1[2*q+1] = fc.y - acc[2*q+1];
            t2[2*q]   = fabsf(fc.x - fh.x);
            t2[2*q+1] = fabsf(fc.y - fh.y);
        }
        *(float4*)&s_t1[pi][cq]     = make_float4(t1[0], t1[1], t1[2], t1[3]);
        *(float4*)&s_t1[pi][cq+4]   = make_float4(t1[4], t1[5], t1[6], t1[7]);
        *(float4*)&s_t2[pi][cq]     = make_float4(t2[0], t2[1], t2[2], t2[3]);
        *(float4*)&s_t2[pi][cq+4]   = make_float4(t2[4], t2[5], t2[6], t2[7]);
    }
    __syncthreads();
    {
        int c = tid;
        float s1 = 0.f, s2 = 0.f;
        #pragma unroll
        for (int q = 0; q < 8; q++) { s1 += s_t1[q][c]; s2 += s_t2[q][c]; }
        atomicAdd(&g_red[h][c], s1);
        atomicAdd(&g_red[h][Cc + c], s2);
    }
}

// ---------------- channel attention for BOTH hists ------------------------------
__global__ void attn_kernel(const float* __restrict__ w1,
                            const float* __restrict__ w2)
{
    __shared__ float s_pool[Cc];
    __shared__ float s_hid[MIDc];
    int tid = threadIdx.x;
    const float inv = 1.f/(float)Pp;
    for (int h = 0; h < 2; h++) {
        s_pool[tid] = g_red[h][tid] * inv;
        __syncthreads();
        if (tid < MIDc) {
            float a = 0.f;
            #pragma unroll 8
            for (int c2 = 0; c2 < Cc; c2++) a += w1[tid*Cc + c2]*s_pool[c2];
            s_hid[tid] = fmaxf(a, 0.f);
        }
        __syncthreads();
        float a = 0.f;
        #pragma unroll
        for (int m = 0; m < MIDc; m++) a += w2[tid*MIDc + m]*s_hid[m];
        g_attn[h][tid] = 1.f/(1.f + expf(-a));
        __syncthreads();
    }
}

// ---- fused = cur + aligned*attn -> padded fp16 (all pixel-major, streaming) ----
__global__ void fuse1T_kernel()
{
    __shared__ float s_attn[Cc];
    int h = blockIdx.y;
    int tid = threadIdx.x;
    if (tid < Cc) s_attn[tid] = g_attn[h][tid];
    __syncthreads();
    const __half* alignedp = g_alignedH + h*Pp*Cc;
    __half* dst = g_padT + h*CH*Cc;
    int idx = blockIdx.x*256 + tid;        // 32 ch-groups per pixel
    int p = idx >> 5;
    int cq = (idx & 31) << 3;
    if (p >= Pp) return;
    uint4 rc = *(const uint4*)(g_xT + p*Cc + cq);
    uint4 ra = *(const uint4*)(alignedp + p*Cc + cq);
    const __half2* hc = (const __half2*)&rc;
    const __half2* ha = (const __half2*)&ra;
    uint4 pk;
    __half2* hp = (__half2*)&pk;
    #pragma unroll
    for (int q = 0; q < 4; q++) {
        float2 fc = __half22float2(hc[q]);
        float2 fa = __half22float2(ha[q]);
        float f0 = fc.x + fa.x*s_attn[cq + 2*q];
        float f1 = fc.y + fa.y*s_attn[cq + 2*q + 1];
        hp[q] = __floats2half2_rn(f0, f1);
    }
    int y = p / Ww, x = p - y*Ww;
    int gp = (y+1)*PW + x + 1;
    *(uint4*)(dst + gp*Cc + cq) = pk;
}

// ---------------- conv3x3: fp16 1-pass, M=64 tile, occ 3, cp.async --------------
#define SA_ELE (9*64*16)
#define STAGE_ELE (SA_ELE + 396*16)
#define STAGE_BYTES (STAGE_ELE*2)
#define CONV_SMEM (2*STAGE_BYTES)

__global__ void __launch_bounds__(256, 3)
conv3x3_mma_kernel(const __half* __restrict__ wh,
                   const __half* __restrict__ in_base,
                   float* __restrict__ out_base,
                   float2* __restrict__ stat_base)
{
    extern __shared__ __half sm2[];
    uint32_t s0 = smem_u32(sm2);

    int z = blockIdx.z;
    const __half* inp = in_base + z*CH*Cc;
    float* out = out_base + z*Cc*Pp;
    float2* stat = stat_base + z*Cc;

    int b0  = blockIdx.x*128;
    int oc0 = blockIdx.y*64;
    int tid = threadIdx.x;
    int wid = tid >> 5, lane = tid & 31;
    int wm = wid & 1, wn = wid >> 1;

    float acc[2][4][4];
    #pragma unroll
    for (int mt = 0; mt < 2; mt++)
        #pragma unroll
        for (int nt = 0; nt < 4; nt++)
            #pragma unroll
            for (int r = 0; r < 4; r++) acc[mt][nt][r] = 0.f;

    int a_lrow = lane & 15;
    int a_ksel = (lane >> 4) & 1;
    int b_tile = lane >> 3;
    int b_r    = lane & 7;
    int b_ntof = (b_tile >> 1)*8;
    int b_ks   = b_tile & 1;

    auto issue = [&](int ic0, int buf) {
        uint32_t base = s0 + buf*STAGE_BYTES;
        uint32_t sbh = base;
        uint32_t sbb = base + SA_ELE*2;
        for (int i = tid; i < 1152; i += 256) {
            int row = i >> 1, half = i & 1;
            int t = row >> 6, m = row & 63;
            int src = (t*Cc + oc0 + m)*Cc + ic0 + half*8;
            cp16(sbh + (uint32_t)((row*16 + half*8)*2), wh + src);
        }
        for (int i = tid; i < 792; i += 256) {
            int row = i >> 1, half = i & 1;
            int prow = row / 132;
            int col  = row - prow*132;
            int src = (b0 + prow*PW + col)*Cc + ic0 + half*8;
            cp16(sbb + (uint32_t)((row*16 + half*8)*2), inp + src);
        }
        CP_COMMIT();
    };

    issue(0, 0);
    for (int s = 0; s < 16; s++) {
        CP_WAIT0();
        __syncthreads();
        if (s < 15) issue((s+1)*16, (s+1) & 1);

        uint32_t base = s0 + (s & 1)*STAGE_BYTES;
        uint32_t sa_h = base;
        uint32_t sb   = base + SA_ELE*2;

        #pragma unroll
        for (int t = 0; t < 9; t++) {
            uint32_t ah[2][4];
            #pragma unroll
            for (int mt = 0; mt < 2; mt++) {
                uint32_t aoff = (uint32_t)(((t*64 + wm*32 + mt*16 + a_lrow)*16 + a_ksel*8)*2);
                ldsm4(ah[mt], sa_h + aoff);
            }
            int posb = (t/3)*132 + (t%3) + wn*32;
            uint32_t bf[4][2];
            #pragma unroll
            for (int np = 0; np < 2; np++) {
                int row = posb + np*16 + b_ntof + b_r;
                uint32_t addr = sb + (uint32_t)((row*16 + b_ks*8)*2);
                uint32_t rr[4];
                ldsm4(rr, addr);
                bf[2*np][0] = rr[0]; bf[2*np][1] = rr[1];
                bf[2*np+1][0] = rr[2]; bf[2*np+1][1] = rr[3];
            }
            #pragma unroll
            for (int mt = 0; mt < 2; mt++)
                #pragma unroll
                for (int nt = 0; nt < 4; nt++)
                    mma16816h(acc[mt][nt], ah[mt][0], ah[mt][1], ah[mt][2], ah[mt][3], bf[nt][0], bf[nt][1]);
        }
        __syncthreads();
    }
    const unsigned FULL = 0xFFFFFFFFu;
    #pragma unroll
    for (int mt = 0; mt < 2; mt++) {
        #pragma unroll
        for (int rh = 0; rh < 2; rh++) {
            int m = oc0 + wm*32 + mt*16 + (lane >> 2) + rh*8;
            float s = 0.f, ss = 0.f;
            #pragma unroll
            for (int nt = 0; nt < 4; nt++) {
                #pragma unroll
                for (int rl = 0; rl < 2; rl++) {
                    float val = acc[mt][nt][rh*2 + rl] * WINV;
                    int n = wn*32 + nt*8 + (lane & 3)*2 + rl;
                    int b = b0 + n;
                    int y = b / PW;
                    int x = b - y*PW;
                    if (b < NB && x < Ww) {
                        out[m*Pp + y*Ww + x] = val;
                        s += val; ss += val*val;
                    }
                }
            }
            s  += __shfl_down_sync(FULL, s, 2);
            s  += __shfl_down_sync(FULL, s, 1);
            ss += __shfl_down_sync(FULL, ss, 2);
            ss += __shfl_down_sync(FULL, ss, 1);
            if ((lane & 3) == 0) {
                atomicAdd(&stat[m].x, s);
                atomicAdd(&stat[m].y, ss);
            }
        }
    }
}

// ---- GN (inline group-stat fold) + weighted fuse -> conv3 input ----------------
__global__ void gn_norm_comb_kernel(const float* __restrict__ gng,
                                    const float* __restrict__ gnb)
{
    __shared__ float tY0[32][33], tY1[32][33];
    __shared__ float s_ms[2][2];
    int p0 = blockIdx.x*32, c0 = blockIdx.y*32;
    int tx = threadIdx.x, ty = threadIdx.y;
    int ltid = ty*32 + tx;
    if (ltid < 64) {
        int h = ltid >> 5, lane = ltid & 31;
        float2 v = g_stat[h*Cc + c0 + lane];
        float s = v.x, ss = v.y;
        #pragma unroll
        for (int o = 16; o > 0; o >>= 1) {
            s  += __shfl_down_sync(0xFFFFFFFFu, s, o);
            ss += __shfl_down_sync(0xFFFFFFFFu, ss, o);
        }
        if (lane == 0) {
            const float N = 32.f*(float)Pp;
            float m = s/N;
            s_ms[h][0] = m;
            s_ms[h][1] = ss/N - m*m;
        }
    }
    #pragma unroll
    for (int i = ty; i < 32; i += 8) {
        int p = p0 + tx;
        tY0[i][tx] = (p < Pp) ? g_y[(c0+i)*Pp + p] : 0.f;
        tY1[i][tx] = (p < Pp) ? g_y[Cc*Pp + (c0+i)*Pp + p] : 0.f;
    }
    __syncthreads();
    int c = c0 + tx;
    const float inv = 1.f/(float)Pp;
    float wgt0 = 1.f/(1.f + expf(g_red[0][Cc + c]*inv));
    float wgt1 = 1.f/(1.f + expf(g_red[1][Cc + c]*inv));
    float winv = 1.f/(wgt0 + wgt1 + 1e-6f);
    float gg = gng[c], gb = gnb[c];
    float m0 = s_ms[0][0], r0 = rsqrtf(s_ms[0][1] + EPSv);
    float m1 = s_ms[1][0], r1 = rsqrtf(s_ms[1][1] + EPSv);
    #pragma unroll
    for (int i = ty; i < 32; i += 8) {
        int p = p0 + i;
        if (p < Pp) {
            float h0 = fmaxf((tY0[tx][i] - m0)*r0*gg + gb, 0.f);
            float h1 = fmaxf((tY1[tx][i] - m1)*r1*gg + gb, 0.f);
            float f = (h0*wgt0 + h1*wgt1) * winv;
            int y = p / Ww, x = p - y*Ww;
            int gp = (y+1)*PW + x + 1;
            g_padT[gp*Cc + c] = __float2half(f);
        }
    }
}

// ---------------- BN normalize + relu -> output ----------------
__global__ void bn_norm_kernel(const float* __restrict__ bng,
                               const float* __restrict__ bnb,
                               float* __restrict__ out)
{
    int i = blockIdx.x*256 + threadIdx.x;
    int c = i / Pp;
    float2 st = g_stat[2*Cc + c];
    float m = st.x * (1.f/(float)Pp);
    float v = st.y * (1.f/(float)Pp) - m*m;
    float o = (g_y[i] - m)*rsqrtf(v + EPSv)*bng[c] + bnb[c];
    out[i] = fmaxf(o, 0.f);
}

// ---------------- host launcher ----------------
extern "C" void kernel_launch(void* const* d_in, const int* in_sizes, int n_in,
                              void* d_out, int out_size)
{
    const float* cur      = (const float*)d_in[0];
    const float* hist0    = (const float*)d_in[1];
    const float* hist1    = (const float*)d_in[2];
    const float* offset_w = (const float*)d_in[3];
    const float* offset_b = (const float*)d_in[4];
    const float* deform_w = (const float*)d_in[5];
    const float* ca_w1    = (const float*)d_in[6];
    const float* ca_w2    = (const float*)d_in[7];
    const float* out_w    = (const float*)d_in[8];
    const float* gn_g     = (const float*)d_in[9];
    const float* gn_b     = (const float*)d_in[10];
    const float* fuse_w   = (const float*)d_in[11];
    const float* bn_g     = (const float*)d_in[12];
    const float* bn_b     = (const float*)d_in[13];
    float* out = (float*)d_out;

    float *p_y;
    float2 *p_stat;
    __half *p_w1h, *p_w2h, *p_padT;
    cudaGetSymbolAddress((void**)&p_y, g_y);
    cudaGetSymbolAddress((void**)&p_stat, g_stat);
    cudaGetSymbolAddress((void**)&p_w1h, g_w1h);
    cudaGetSymbolAddress((void**)&p_w2h, g_w2h);
    cudaGetSymbolAddress((void**)&p_padT, g_padT);

    cudaFuncSetAttribute(conv3x3_mma_kernel,
                         cudaFuncAttributeMaxDynamicSharedMemorySize, CONV_SMEM);

    dim3 tGrid(313, 8, 3), tBlock(32, 8);
    dim3 gnGrid(313, 8);
    dim3 offGrid(79, 2, 2);
    dim3 convGrid(80, 4, 2);
    dim3 conv3Grid(80, 4, 1);
    const int NW = Cc*Cc*9;
    const int PREP_TOT = 2*NW + 64*512 + Tt*Cc + 2*CH*Cc;

    split_xT_kernel<<<tGrid, tBlock>>>(cur, hist0, hist1);                    // 0
    prep_w_kernel<<<(PREP_TOT + 255)/256, 256>>>(out_w, fuse_w, offset_w, deform_w); // 1
    offset_mma_kernel<<<offGrid, 256>>>(offset_b);                            // 2
    deform_kernel<<<dim3(1250, 2), 256>>>();                                  // 3 (profiled)
    attn_kernel<<<1, Cc>>>(ca_w1, ca_w2);                                     // 4
    fuse1T_kernel<<<dim3(1250, 2), 256>>>();                                  // 5
    conv3x3_mma_kernel<<<convGrid, 256, CONV_SMEM>>>(p_w1h, p_padT, p_y, p_stat); // 6
    gn_norm_comb_kernel<<<gnGrid, tBlock>>>(gn_g, gn_b);                      // 7
    conv3x3_mma_kernel<<<conv3Grid, 256, CONV_SMEM>>>(p_w2h, p_padT, p_y, p_stat + 2*Cc); // 8
    bn_norm_kernel<<<Cc*Pp/256, 256>>>(bn_g, bn_b, out);                      // 9
}